// round 3
// baseline (speedup 1.0000x reference)
#include <cuda_runtime.h>
#include <cstdint>

#define N_NODES 16384
#define N_EDGES 262144
#define N_GRAPHS 16
#define IN_CH 128
#define HID_CH 256
#define LAT 64

// ---- output layout (tuple flattened, all fp32) ----
// z_node  [16384,64]   @ 0
// z_graph [16,64]      @ 1048576
// x_hat   [16384,128]  @ 1049600
// a_hat   [16384,16384]@ 3146752

// ---- device scratch (no allocations allowed) ----
__device__ float g_dinv[N_NODES];
__device__ __align__(16) float g_xs [N_NODES * IN_CH];   // dinv[r] * x[r]
__device__ __align__(16) float g_agg[N_NODES * IN_CH];   // sum incoming + self
__device__ __align__(16) float g_h  [N_NODES * HID_CH];  // relu hidden
__device__ float g_zsum[N_GRAPHS * LAT];
__device__ float g_cnt [N_GRAPHS];
__device__ __align__(16) float g_xg  [N_GRAPHS * IN_CH]; // decoded per-graph row

// ============================================================
// small kernels
// ============================================================
__global__ void k_init() {
    int i = blockIdx.x * blockDim.x + threadIdx.x;
    if (i < N_NODES) g_dinv[i] = 1.0f;               // self-loop degree
    if (i < N_GRAPHS * LAT) g_zsum[i] = 0.0f;
    if (i < N_GRAPHS) g_cnt[i] = 0.0f;
}

// NOTE: edge_index / batch are int32 (JAX default x64-disabled)
__global__ void k_degree(const int* __restrict__ ei) {
    int e = blockIdx.x * blockDim.x + threadIdx.x;
    if (e < N_EDGES) atomicAdd(&g_dinv[ei[N_EDGES + e]], 1.0f);
}

__global__ void k_rsqrt() {
    int i = blockIdx.x * blockDim.x + threadIdx.x;
    if (i < N_NODES) g_dinv[i] = rsqrtf(g_dinv[i]);  // deg >= 1 always
}

// xs = dinv * x ; agg initialized with self-loop term (= xs)
__global__ void k_scale(const float4* __restrict__ x4) {
    int idx = blockIdx.x * blockDim.x + threadIdx.x; // < N_NODES*32
    int node = idx >> 5;
    float d = g_dinv[node];
    float4 v = x4[idx];
    v.x *= d; v.y *= d; v.z *= d; v.w *= d;
    ((float4*)g_xs)[idx] = v;
    ((float4*)g_agg)[idx] = v;
}

// one warp per edge: 32 lanes x 4 floats = 128 channels; scalar global atomics
__global__ void k_scatter(const int* __restrict__ ei) {
    int gid = blockIdx.x * blockDim.x + threadIdx.x;
    int e = gid >> 5;
    int lane = gid & 31;
    if (e >= N_EDGES) return;
    int r = ei[e];
    int c = ei[N_EDGES + e];
    float4 v = ((const float4*)g_xs)[r * 32 + lane];
    float* dst = g_agg + c * IN_CH + lane * 4;
    atomicAdd(dst + 0, v.x);
    atomicAdd(dst + 1, v.y);
    atomicAdd(dst + 2, v.z);
    atomicAdd(dst + 3, v.w);
}

// ============================================================
// GEMM1: h = relu( (dinv .* agg)[16384,128] @ gcn_w[256,128]^T + gcn_b )
// ============================================================
__global__ void k_gemm1(const float* __restrict__ W, const float* __restrict__ bias) {
    __shared__ float As[128][33];
    __shared__ float Bs[128][33];
    int m0 = blockIdx.y * 128, n0 = blockIdx.x * 128;
    int tid = threadIdx.x;
    int tx = tid & 15, ty = tid >> 4;
    float acc[8][8];
#pragma unroll
    for (int i = 0; i < 8; i++)
#pragma unroll
        for (int j = 0; j < 8; j++) acc[i][j] = 0.0f;

    for (int kc = 0; kc < IN_CH; kc += 32) {
#pragma unroll
        for (int it = 0; it < 4; ++it) {
            int idx = tid + it * 256;  // 1024 float4 in 128x32 tile
            int row = idx >> 3, q = idx & 7;
            float4 v = ((const float4*)g_agg)[(m0 + row) * (IN_CH / 4) + (kc >> 2) + q];
            float d = g_dinv[m0 + row];
            As[row][q * 4 + 0] = v.x * d; As[row][q * 4 + 1] = v.y * d;
            As[row][q * 4 + 2] = v.z * d; As[row][q * 4 + 3] = v.w * d;
        }
#pragma unroll
        for (int it = 0; it < 4; ++it) {
            int idx = tid + it * 256;
            int row = idx >> 3, q = idx & 7;
            float4 v = ((const float4*)W)[(n0 + row) * (IN_CH / 4) + (kc >> 2) + q];
            Bs[row][q * 4 + 0] = v.x; Bs[row][q * 4 + 1] = v.y;
            Bs[row][q * 4 + 2] = v.z; Bs[row][q * 4 + 3] = v.w;
        }
        __syncthreads();
#pragma unroll
        for (int kk = 0; kk < 32; ++kk) {
            float ra[8], rb[8];
#pragma unroll
            for (int i = 0; i < 8; i++) ra[i] = As[ty * 8 + i][kk];
#pragma unroll
            for (int j = 0; j < 8; j++) rb[j] = Bs[tx * 8 + j][kk];
#pragma unroll
            for (int i = 0; i < 8; i++)
#pragma unroll
                for (int j = 0; j < 8; j++) acc[i][j] = fmaf(ra[i], rb[j], acc[i][j]);
        }
        __syncthreads();
    }
#pragma unroll
    for (int i = 0; i < 8; i++) {
        int m = m0 + ty * 8 + i;
#pragma unroll
        for (int j = 0; j < 8; j++) {
            int n = n0 + tx * 8 + j;
            g_h[m * HID_CH + n] = fmaxf(acc[i][j] + bias[n], 0.0f);
        }
    }
}

// ============================================================
// GEMM2: z_node = h[16384,256] @ lin_w[64,256]^T + lin_b
// ============================================================
__global__ void k_gemm2(const float* __restrict__ W, const float* __restrict__ bias,
                        float* __restrict__ Z) {
    __shared__ float As[128][33];
    __shared__ float Bs[64][33];
    int m0 = blockIdx.y * 128;
    int tid = threadIdx.x;
    int tx = tid & 15, ty = tid >> 4;
    float acc[8][4];
#pragma unroll
    for (int i = 0; i < 8; i++)
#pragma unroll
        for (int j = 0; j < 4; j++) acc[i][j] = 0.0f;

    for (int kc = 0; kc < HID_CH; kc += 32) {
#pragma unroll
        for (int it = 0; it < 4; ++it) {
            int idx = tid + it * 256;
            int row = idx >> 3, q = idx & 7;
            float4 v = ((const float4*)g_h)[(m0 + row) * (HID_CH / 4) + (kc >> 2) + q];
            As[row][q * 4 + 0] = v.x; As[row][q * 4 + 1] = v.y;
            As[row][q * 4 + 2] = v.z; As[row][q * 4 + 3] = v.w;
        }
#pragma unroll
        for (int it = 0; it < 2; ++it) {
            int idx = tid + it * 256;  // 512 float4 in 64x32 tile
            int row = idx >> 3, q = idx & 7;
            float4 v = ((const float4*)W)[row * (HID_CH / 4) + (kc >> 2) + q];
            Bs[row][q * 4 + 0] = v.x; Bs[row][q * 4 + 1] = v.y;
            Bs[row][q * 4 + 2] = v.z; Bs[row][q * 4 + 3] = v.w;
        }
        __syncthreads();
#pragma unroll
        for (int kk = 0; kk < 32; ++kk) {
            float ra[8], rb[4];
#pragma unroll
            for (int i = 0; i < 8; i++) ra[i] = As[ty * 8 + i][kk];
#pragma unroll
            for (int j = 0; j < 4; j++) rb[j] = Bs[tx * 4 + j][kk];
#pragma unroll
            for (int i = 0; i < 8; i++)
#pragma unroll
                for (int j = 0; j < 4; j++) acc[i][j] = fmaf(ra[i], rb[j], acc[i][j]);
        }
        __syncthreads();
    }
#pragma unroll
    for (int i = 0; i < 8; i++) {
        int m = m0 + ty * 8 + i;
#pragma unroll
        for (int j = 0; j < 4; j++) {
            int n = tx * 4 + j;
            Z[m * LAT + n] = acc[i][j] + bias[n];
        }
    }
}

// ============================================================
// pooling (shared-mem partials, then global atomics)
// ============================================================
__global__ void k_pool(const float* __restrict__ Z, const int* __restrict__ batch) {
    __shared__ float ssum[N_GRAPHS * LAT];
    __shared__ float scnt[N_GRAPHS];
    int tid = threadIdx.x;  // 256
    for (int i = tid; i < N_GRAPHS * LAT; i += 256) ssum[i] = 0.0f;
    if (tid < N_GRAPHS) scnt[tid] = 0.0f;
    __syncthreads();
    int base = blockIdx.x * 1024;
    int k = tid & 63, sub = tid >> 6;
    for (int i0 = 0; i0 < 1024; i0 += 4) {
        int node = base + i0 + sub;
        int g = batch[node];
        atomicAdd(&ssum[g * LAT + k], Z[node * LAT + k]);
        if (k == 0) atomicAdd(&scnt[g], 1.0f);
    }
    __syncthreads();
    for (int i = tid; i < N_GRAPHS * LAT; i += 256) atomicAdd(&g_zsum[i], ssum[i]);
    if (tid < N_GRAPHS) atomicAdd(&g_cnt[tid], scnt[tid]);
}

__global__ void k_zg(float* __restrict__ z_graph) {
    int i = blockIdx.x * blockDim.x + threadIdx.x;
    if (i < N_GRAPHS * LAT) {
        int g = i / LAT;
        z_graph[i] = g_zsum[i] / fmaxf(g_cnt[g], 1.0f);
    }
}

__global__ void k_xg(const float* __restrict__ z_graph,
                     const float* __restrict__ dec_w, const float* __restrict__ dec_b) {
    int i = blockIdx.x * blockDim.x + threadIdx.x;  // < 2048
    if (i >= N_GRAPHS * IN_CH) return;
    int g = i / IN_CH, c = i % IN_CH;
    float s = dec_b[c];
#pragma unroll
    for (int k = 0; k < LAT; k++) s = fmaf(z_graph[g * LAT + k], dec_w[c * LAT + k], s);
    g_xg[i] = s;
}

__global__ void k_xhat(const int* __restrict__ batch, float* __restrict__ x_hat) {
    int idx = blockIdx.x * blockDim.x + threadIdx.x;  // < N_NODES*32
    int node = idx >> 5;
    int g = batch[node];
    ((float4*)x_hat)[idx] = ((const float4*)g_xg)[g * 32 + (idx & 31)];
}

// ============================================================
// a_hat = sigmoid(Z @ Z^T), tf32 mma.sync m16n8k8
// block tile 128x128, 8 warps (2x4), warp tile 64x32, K=64 resident in smem
// ============================================================
__device__ __forceinline__ uint32_t f2tf32(float f) {
    uint32_t u;
    asm("cvt.rna.tf32.f32 %0, %1;" : "=r"(u) : "f"(f));
    return u;
}
__device__ __forceinline__ float fsig(float x) {
    return __fdividef(1.0f, 1.0f + __expf(-x));
}

#define AH_LD 68  // pad so row-strided column reads spread across banks

__global__ __launch_bounds__(256, 2) void k_ahat(const float* __restrict__ Z,
                                                 float* __restrict__ out) {
    extern __shared__ uint32_t smbuf[];
    uint32_t* As = smbuf;                 // [128][AH_LD]
    uint32_t* Bs = smbuf + 128 * AH_LD;   // [128][AH_LD]
    int bm = blockIdx.y, bn = blockIdx.x;
    int tid = threadIdx.x;
    const float4* Z4 = (const float4*)Z;

#pragma unroll
    for (int it = 0; it < 8; ++it) {
        int idx = tid + it * 256;       // 2048 float4 per tile
        int row = idx >> 4, q = idx & 15;
        float4 va = Z4[(bm * 128 + row) * 16 + q];
        As[row * AH_LD + q * 4 + 0] = f2tf32(va.x);
        As[row * AH_LD + q * 4 + 1] = f2tf32(va.y);
        As[row * AH_LD + q * 4 + 2] = f2tf32(va.z);
        As[row * AH_LD + q * 4 + 3] = f2tf32(va.w);
        float4 vb = Z4[(bn * 128 + row) * 16 + q];
        Bs[row * AH_LD + q * 4 + 0] = f2tf32(vb.x);
        Bs[row * AH_LD + q * 4 + 1] = f2tf32(vb.y);
        Bs[row * AH_LD + q * 4 + 2] = f2tf32(vb.z);
        Bs[row * AH_LD + q * 4 + 3] = f2tf32(vb.w);
    }
    __syncthreads();

    int warp = tid >> 5, lane = tid & 31;
    int wm = (warp >> 2) * 64;   // warp m-origin within block (0 or 64)
    int wn = (warp & 3) * 32;    // warp n-origin within block
    int gp = lane >> 2, tq = lane & 3;

    float acc[4][4][4];
#pragma unroll
    for (int mt = 0; mt < 4; mt++)
#pragma unroll
        for (int nt = 0; nt < 4; nt++)
#pragma unroll
            for (int r = 0; r < 4; r++) acc[mt][nt][r] = 0.0f;

#pragma unroll
    for (int ks = 0; ks < 8; ++ks) {
        int kb = ks * 8;
        uint32_t a[4][4], b[4][2];
#pragma unroll
        for (int mt = 0; mt < 4; ++mt) {
            int r0 = wm + mt * 16 + gp;
            a[mt][0] = As[r0 * AH_LD + kb + tq];
            a[mt][1] = As[(r0 + 8) * AH_LD + kb + tq];
            a[mt][2] = As[r0 * AH_LD + kb + tq + 4];
            a[mt][3] = As[(r0 + 8) * AH_LD + kb + tq + 4];
        }
#pragma unroll
        for (int nt = 0; nt < 4; ++nt) {
            int c0 = wn + nt * 8 + gp;
            b[nt][0] = Bs[c0 * AH_LD + kb + tq];
            b[nt][1] = Bs[c0 * AH_LD + kb + tq + 4];
        }
#pragma unroll
        for (int mt = 0; mt < 4; ++mt)
#pragma unroll
            for (int nt = 0; nt < 4; ++nt) {
                asm volatile(
                    "mma.sync.aligned.m16n8k8.row.col.f32.tf32.tf32.f32 "
                    "{%0,%1,%2,%3}, {%4,%5,%6,%7}, {%8,%9}, {%0,%1,%2,%3};"
                    : "+f"(acc[mt][nt][0]), "+f"(acc[mt][nt][1]),
                      "+f"(acc[mt][nt][2]), "+f"(acc[mt][nt][3])
                    : "r"(a[mt][0]), "r"(a[mt][1]), "r"(a[mt][2]), "r"(a[mt][3]),
                      "r"(b[nt][0]), "r"(b[nt][1]));
            }
    }

#pragma unroll
    for (int mt = 0; mt < 4; ++mt)
#pragma unroll
        for (int nt = 0; nt < 4; ++nt) {
            int row = bm * 128 + wm + mt * 16 + gp;
            int col = bn * 128 + wn + nt * 8 + tq * 2;
            float2 v;
            v.x = fsig(acc[mt][nt][0]);
            v.y = fsig(acc[mt][nt][1]);
            *(float2*)(out + (size_t)row * N_NODES + col) = v;
            v.x = fsig(acc[mt][nt][2]);
            v.y = fsig(acc[mt][nt][3]);
            *(float2*)(out + (size_t)(row + 8) * N_NODES + col) = v;
        }
}

// ============================================================
// launch
// ============================================================
extern "C" void kernel_launch(void* const* d_in, const int* in_sizes, int n_in,
                              void* d_out, int out_size) {
    const float* x     = (const float*)d_in[0];
    const int*   ei    = (const int*)d_in[1];    // int32 (JAX default x64 off)
    const int*   batch = (const int*)d_in[2];    // int32
    const float* gcn_w = (const float*)d_in[3];
    const float* gcn_b = (const float*)d_in[4];
    const float* lin_w = (const float*)d_in[5];
    const float* lin_b = (const float*)d_in[6];
    const float* dec_w = (const float*)d_in[7];
    const float* dec_b = (const float*)d_in[8];

    float* out     = (float*)d_out;
    float* z_node  = out;
    float* z_graph = out + 1048576;
    float* x_hat   = out + 1049600;
    float* a_hat   = out + 3146752;

    const int AH_SMEM = 2 * 128 * AH_LD * 4;  // 69632 B
    cudaFuncSetAttribute(k_ahat, cudaFuncAttributeMaxDynamicSharedMemorySize, AH_SMEM);

    k_init<<<64, 256>>>();
    k_degree<<<1024, 256>>>(ei);
    k_rsqrt<<<64, 256>>>();
    k_scale<<<2048, 256>>>((const float4*)x);
    k_scatter<<<32768, 256>>>(ei);
    k_gemm1<<<dim3(2, 128), 256>>>(gcn_w, gcn_b);
    k_gemm2<<<dim3(1, 128), 256>>>(lin_w, lin_b, z_node);
    k_pool<<<16, 256>>>(z_node, batch);
    k_zg<<<4, 256>>>(z_graph);
    k_xg<<<8, 256>>>(z_graph, dec_w, dec_b);
    k_xhat<<<2048, 256>>>(batch, x_hat);
    k_ahat<<<dim3(128, 128), 256, AH_SMEM>>>(z_node, a_hat);
}

// round 4
// speedup vs baseline: 2.2117x; 2.2117x over previous
#include <cuda_runtime.h>
#include <cstdint>
#include <cmath>

#define N_NODES 16384
#define N_EDGES 262144
#define N_GRAPHS 16
#define IN_CH 128
#define HID_CH 256
#define LAT 64

// ---- output layout (tuple flattened, all fp32) ----
// z_node  [16384,64]   @ 0
// z_graph [16,64]      @ 1048576
// x_hat   [16384,128]  @ 1049600
// a_hat   [16384,16384]@ 3146752

// ---- device scratch ----
__device__ float g_dinv[N_NODES];                        // degree, then rsqrt(degree)
__device__ __align__(16) float g_xs [N_NODES * IN_CH];   // dinv[r] * x[r]
__device__ __align__(16) float g_agg[N_NODES * IN_CH];   // sum incoming + self
__device__ __align__(16) float g_h  [N_NODES * HID_CH];  // relu hidden
__device__ __align__(16) float g_xg [N_GRAPHS * IN_CH];  // decoded per-graph row

// ============================================================
__global__ void k_init() {
    int i = blockIdx.x * blockDim.x + threadIdx.x;
    if (i < N_NODES) g_dinv[i] = 1.0f;               // self-loop degree
}

__global__ void k_degree(const int* __restrict__ ei) {
    int e = blockIdx.x * blockDim.x + threadIdx.x;
    if (e < N_EDGES) atomicAdd(&g_dinv[ei[N_EDGES + e]], 1.0f);
}

// d = rsqrt(deg); xs = d*x ; agg init = xs (self loop); store d back
__global__ void k_scale(const float4* __restrict__ x4) {
    int idx = blockIdx.x * blockDim.x + threadIdx.x; // < N_NODES*32
    int node = idx >> 5;
    int lane = idx & 31;
    float d = rsqrtf(g_dinv[node]);   // all 32 lanes of this node read first...
    float4 v = x4[idx];
    v.x *= d; v.y *= d; v.z *= d; v.w *= d;
    ((float4*)g_xs)[idx] = v;
    ((float4*)g_agg)[idx] = v;
    if (lane == 0) g_dinv[node] = d;  // ...then one lane writes (same warp, later in program order)
}

// one warp per edge: 32 lanes x float4 = 128 channels; vector global atomics
__global__ void k_scatter(const int* __restrict__ ei) {
    int gid = blockIdx.x * blockDim.x + threadIdx.x;
    int e = gid >> 5;
    int lane = gid & 31;
    if (e >= N_EDGES) return;
    int r = ei[e];
    int c = ei[N_EDGES + e];
    float4 v = ((const float4*)g_xs)[r * 32 + lane];
    atomicAdd((float4*)(g_agg + c * IN_CH + lane * 4), v);
}

// ============================================================
// GEMM1: h = relu( (dinv .* agg)[16384,128] @ gcn_w[256,128]^T + gcn_b )
// ============================================================
__global__ void k_gemm1(const float* __restrict__ W, const float* __restrict__ bias) {
    __shared__ float As[128][33];
    __shared__ float Bs[128][33];
    int m0 = blockIdx.y * 128, n0 = blockIdx.x * 128;
    int tid = threadIdx.x;
    int tx = tid & 15, ty = tid >> 4;
    float acc[8][8];
#pragma unroll
    for (int i = 0; i < 8; i++)
#pragma unroll
        for (int j = 0; j < 8; j++) acc[i][j] = 0.0f;

    for (int kc = 0; kc < IN_CH; kc += 32) {
#pragma unroll
        for (int it = 0; it < 4; ++it) {
            int idx = tid + it * 256;
            int row = idx >> 3, q = idx & 7;
            float4 v = ((const float4*)g_agg)[(m0 + row) * (IN_CH / 4) + (kc >> 2) + q];
            float d = g_dinv[m0 + row];
            As[row][q * 4 + 0] = v.x * d; As[row][q * 4 + 1] = v.y * d;
            As[row][q * 4 + 2] = v.z * d; As[row][q * 4 + 3] = v.w * d;
        }
#pragma unroll
        for (int it = 0; it < 4; ++it) {
            int idx = tid + it * 256;
            int row = idx >> 3, q = idx & 7;
            float4 v = ((const float4*)W)[(n0 + row) * (IN_CH / 4) + (kc >> 2) + q];
            Bs[row][q * 4 + 0] = v.x; Bs[row][q * 4 + 1] = v.y;
            Bs[row][q * 4 + 2] = v.z; Bs[row][q * 4 + 3] = v.w;
        }
        __syncthreads();
#pragma unroll
        for (int kk = 0; kk < 32; ++kk) {
            float ra[8], rb[8];
#pragma unroll
            for (int i = 0; i < 8; i++) ra[i] = As[ty * 8 + i][kk];
#pragma unroll
            for (int j = 0; j < 8; j++) rb[j] = Bs[tx * 8 + j][kk];
#pragma unroll
            for (int i = 0; i < 8; i++)
#pragma unroll
                for (int j = 0; j < 8; j++) acc[i][j] = fmaf(ra[i], rb[j], acc[i][j]);
        }
        __syncthreads();
    }
#pragma unroll
    for (int i = 0; i < 8; i++) {
        int m = m0 + ty * 8 + i;
#pragma unroll
        for (int j = 0; j < 8; j++) {
            int n = n0 + tx * 8 + j;
            g_h[m * HID_CH + n] = fmaxf(acc[i][j] + bias[n], 0.0f);
        }
    }
}

// ============================================================
// GEMM2: z_node = h[16384,256] @ lin_w[64,256]^T + lin_b
// ============================================================
__global__ void k_gemm2(const float* __restrict__ W, const float* __restrict__ bias,
                        float* __restrict__ Z) {
    __shared__ float As[128][33];
    __shared__ float Bs[64][33];
    int m0 = blockIdx.y * 128;
    int tid = threadIdx.x;
    int tx = tid & 15, ty = tid >> 4;
    float acc[8][4];
#pragma unroll
    for (int i = 0; i < 8; i++)
#pragma unroll
        for (int j = 0; j < 4; j++) acc[i][j] = 0.0f;

    for (int kc = 0; kc < HID_CH; kc += 32) {
#pragma unroll
        for (int it = 0; it < 4; ++it) {
            int idx = tid + it * 256;
            int row = idx >> 3, q = idx & 7;
            float4 v = ((const float4*)g_h)[(m0 + row) * (HID_CH / 4) + (kc >> 2) + q];
            As[row][q * 4 + 0] = v.x; As[row][q * 4 + 1] = v.y;
            As[row][q * 4 + 2] = v.z; As[row][q * 4 + 3] = v.w;
        }
#pragma unroll
        for (int it = 0; it < 2; ++it) {
            int idx = tid + it * 256;
            int row = idx >> 3, q = idx & 7;
            float4 v = ((const float4*)W)[row * (HID_CH / 4) + (kc >> 2) + q];
            Bs[row][q * 4 + 0] = v.x; Bs[row][q * 4 + 1] = v.y;
            Bs[row][q * 4 + 2] = v.z; Bs[row][q * 4 + 3] = v.w;
        }
        __syncthreads();
#pragma unroll
        for (int kk = 0; kk < 32; ++kk) {
            float ra[8], rb[4];
#pragma unroll
            for (int i = 0; i < 8; i++) ra[i] = As[ty * 8 + i][kk];
#pragma unroll
            for (int j = 0; j < 4; j++) rb[j] = Bs[tx * 4 + j][kk];
#pragma unroll
            for (int i = 0; i < 8; i++)
#pragma unroll
                for (int j = 0; j < 4; j++) acc[i][j] = fmaf(ra[i], rb[j], acc[i][j]);
        }
        __syncthreads();
    }
#pragma unroll
    for (int i = 0; i < 8; i++) {
        int m = m0 + ty * 8 + i;
#pragma unroll
        for (int j = 0; j < 4; j++) {
            int n = tx * 4 + j;
            Z[m * LAT + n] = acc[i][j] + bias[n];
        }
    }
}

// ============================================================
// fused pool + z_graph + decoded graph rows.  batch is SORTED -> binary search
// boundaries, register accumulation, zero atomics. 16 blocks x 256 threads.
// ============================================================
__global__ void k_poolfused(const float* __restrict__ Z, const int* __restrict__ batch,
                            float* __restrict__ z_graph,
                            const float* __restrict__ dec_w, const float* __restrict__ dec_b) {
    __shared__ float red[4][LAT];
    __shared__ float zg[LAT];
    int g = blockIdx.x;
    int tid = threadIdx.x;
    int k = tid & 63, sub = tid >> 6;

    int lo = 0, hi = N_NODES;
    while (lo < hi) { int mid = (lo + hi) >> 1; if (batch[mid] < g) lo = mid + 1; else hi = mid; }
    int start = lo;
    hi = N_NODES;
    while (lo < hi) { int mid = (lo + hi) >> 1; if (batch[mid] < g + 1) lo = mid + 1; else hi = mid; }
    int end = lo;

    float acc = 0.0f;
    for (int n = start + sub; n < end; n += 4) acc += Z[n * LAT + k];
    red[sub][k] = acc;
    __syncthreads();
    if (sub == 0) {
        float s = red[0][k] + red[1][k] + red[2][k] + red[3][k];
        float zv = s / fmaxf((float)(end - start), 1.0f);
        z_graph[g * LAT + k] = zv;
        zg[k] = zv;
    }
    __syncthreads();
    if (tid < IN_CH) {
        float s = dec_b[tid];
#pragma unroll
        for (int kk = 0; kk < LAT; kk++) s = fmaf(zg[kk], dec_w[tid * LAT + kk], s);
        g_xg[g * IN_CH + tid] = s;
    }
}

__global__ void k_xhat(const int* __restrict__ batch, float* __restrict__ x_hat) {
    int idx = blockIdx.x * blockDim.x + threadIdx.x;  // < N_NODES*32
    int node = idx >> 5;
    int g = batch[node];
    ((float4*)x_hat)[idx] = ((const float4*)g_xg)[g * 32 + (idx & 31)];
}

// ============================================================
// a_hat = sigmoid(Z @ Z^T): SYMMETRIC -> compute upper-tri tiles only,
// mirror off-diagonal tiles through an smem transpose with float4 stores.
// tf32 mma.sync m16n8k8, block tile 128x128, 8 warps, K=64 smem-resident.
// ============================================================
__device__ __forceinline__ uint32_t f2tf32(float f) {
    uint32_t u;
    asm("cvt.rna.tf32.f32 %0, %1;" : "=r"(u) : "f"(f));
    return u;
}
__device__ __forceinline__ float fsig(float x) {
    return __fdividef(1.0f, 1.0f + __expf(-x));
}

#define AH_LD 68          // tf32 tile pitch (uint32)
#define AH_TLD 132        // transpose staging pitch (float), %4==0, odd/32 spread
#define AH_NTILE 128      // 16384/128
#define AH_NBLK (AH_NTILE * (AH_NTILE + 1) / 2)   // 8256

__global__ __launch_bounds__(256, 2) void k_ahat(const float* __restrict__ Z,
                                                 float* __restrict__ out) {
    extern __shared__ uint32_t smbuf[];
    uint32_t* As = smbuf;                 // [128][AH_LD]
    uint32_t* Bs = smbuf + 128 * AH_LD;   // [128][AH_LD]

    // decode linear block -> (bm<=bn) upper-tri pair: L = bn*(bn+1)/2 + bm
    int L = blockIdx.x;
    int bn = (int)((sqrt(8.0 * (double)L + 1.0) - 1.0) * 0.5);
    while ((bn + 1) * (bn + 2) / 2 <= L) bn++;
    while (bn * (bn + 1) / 2 > L) bn--;
    int bm = L - bn * (bn + 1) / 2;

    int tid = threadIdx.x;
    const float4* Z4 = (const float4*)Z;

#pragma unroll
    for (int it = 0; it < 8; ++it) {
        int idx = tid + it * 256;       // 2048 float4 per tile
        int row = idx >> 4, q = idx & 15;
        float4 va = Z4[(bm * 128 + row) * 16 + q];
        As[row * AH_LD + q * 4 + 0] = f2tf32(va.x);
        As[row * AH_LD + q * 4 + 1] = f2tf32(va.y);
        As[row * AH_LD + q * 4 + 2] = f2tf32(va.z);
        As[row * AH_LD + q * 4 + 3] = f2tf32(va.w);
        float4 vb = Z4[(bn * 128 + row) * 16 + q];
        Bs[row * AH_LD + q * 4 + 0] = f2tf32(vb.x);
        Bs[row * AH_LD + q * 4 + 1] = f2tf32(vb.y);
        Bs[row * AH_LD + q * 4 + 2] = f2tf32(vb.z);
        Bs[row * AH_LD + q * 4 + 3] = f2tf32(vb.w);
    }
    __syncthreads();

    int warp = tid >> 5, lane = tid & 31;
    int wm = (warp >> 2) * 64;
    int wn = (warp & 3) * 32;
    int gp = lane >> 2, tq = lane & 3;

    float acc[4][4][4];
#pragma unroll
    for (int mt = 0; mt < 4; mt++)
#pragma unroll
        for (int nt = 0; nt < 4; nt++)
#pragma unroll
            for (int r = 0; r < 4; r++) acc[mt][nt][r] = 0.0f;

#pragma unroll
    for (int ks = 0; ks < 8; ++ks) {
        int kb = ks * 8;
        uint32_t a[4][4], b[4][2];
#pragma unroll
        for (int mt = 0; mt < 4; ++mt) {
            int r0 = wm + mt * 16 + gp;
            a[mt][0] = As[r0 * AH_LD + kb + tq];
            a[mt][1] = As[(r0 + 8) * AH_LD + kb + tq];
            a[mt][2] = As[r0 * AH_LD + kb + tq + 4];
            a[mt][3] = As[(r0 + 8) * AH_LD + kb + tq + 4];
        }
#pragma unroll
        for (int nt = 0; nt < 4; ++nt) {
            int c0 = wn + nt * 8 + gp;
            b[nt][0] = Bs[c0 * AH_LD + kb + tq];
            b[nt][1] = Bs[c0 * AH_LD + kb + tq + 4];
        }
#pragma unroll
        for (int mt = 0; mt < 4; ++mt)
#pragma unroll
            for (int nt = 0; nt < 4; ++nt) {
                asm volatile(
                    "mma.sync.aligned.m16n8k8.row.col.f32.tf32.tf32.f32 "
                    "{%0,%1,%2,%3}, {%4,%5,%6,%7}, {%8,%9}, {%0,%1,%2,%3};"
                    : "+f"(acc[mt][nt][0]), "+f"(acc[mt][nt][1]),
                      "+f"(acc[mt][nt][2]), "+f"(acc[mt][nt][3])
                    : "r"(a[mt][0]), "r"(a[mt][1]), "r"(a[mt][2]), "r"(a[mt][3]),
                      "r"(b[nt][0]), "r"(b[nt][1]));
            }
    }

    // sigmoid in-place, then direct (row-major) tile store
#pragma unroll
    for (int mt = 0; mt < 4; ++mt)
#pragma unroll
        for (int nt = 0; nt < 4; ++nt) {
#pragma unroll
            for (int r = 0; r < 4; ++r) acc[mt][nt][r] = fsig(acc[mt][nt][r]);
            int row = bm * 128 + wm + mt * 16 + gp;
            int col = bn * 128 + wn + nt * 8 + tq * 2;
            float2 v;
            v.x = acc[mt][nt][0]; v.y = acc[mt][nt][1];
            *(float2*)(out + (size_t)row * N_NODES + col) = v;
            v.x = acc[mt][nt][2]; v.y = acc[mt][nt][3];
            *(float2*)(out + (size_t)(row + 8) * N_NODES + col) = v;
        }

    // mirrored tile: transpose through smem (reuse As/Bs), coalesced float4 out
    if (bm != bn) {
        __syncthreads();                  // everyone is done reading As/Bs
        float* S = (float*)smbuf;         // [128][AH_TLD], 67584 B <= 69632 B
#pragma unroll
        for (int mt = 0; mt < 4; ++mt)
#pragma unroll
            for (int nt = 0; nt < 4; ++nt) {
                int rl = wm + mt * 16 + gp;
                int cl = wn + nt * 8 + tq * 2;
                S[cl * AH_TLD + rl]           = acc[mt][nt][0];
                S[(cl + 1) * AH_TLD + rl]     = acc[mt][nt][1];
                S[cl * AH_TLD + rl + 8]       = acc[mt][nt][2];
                S[(cl + 1) * AH_TLD + rl + 8] = acc[mt][nt][3];
            }
        __syncthreads();
#pragma unroll
        for (int it = 0; it < 16; ++it) {
            int idx = tid + it * 256;     // 4096 float4
            int rt = idx >> 5, q = idx & 31;
            float4 w = *(const float4*)(S + rt * AH_TLD + q * 4);
            *(float4*)(out + (size_t)(bn * 128 + rt) * N_NODES + bm * 128 + q * 4) = w;
        }
    }
}

// ============================================================
// launch
// ============================================================
extern "C" void kernel_launch(void* const* d_in, const int* in_sizes, int n_in,
                              void* d_out, int out_size) {
    const float* x     = (const float*)d_in[0];
    const int*   ei    = (const int*)d_in[1];    // int32 (JAX default x64 off)
    const int*   batch = (const int*)d_in[2];    // int32, sorted
    const float* gcn_w = (const float*)d_in[3];
    const float* gcn_b = (const float*)d_in[4];
    const float* lin_w = (const float*)d_in[5];
    const float* lin_b = (const float*)d_in[6];
    const float* dec_w = (const float*)d_in[7];
    const float* dec_b = (const float*)d_in[8];

    float* out     = (float*)d_out;
    float* z_node  = out;
    float* z_graph = out + 1048576;
    float* x_hat   = out + 1049600;
    float* a_hat   = out + 3146752;

    const int AH_SMEM = 2 * 128 * AH_LD * 4;  // 69632 B
    cudaFuncSetAttribute(k_ahat, cudaFuncAttributeMaxDynamicSharedMemorySize, AH_SMEM);

    k_init<<<64, 256>>>();
    k_degree<<<1024, 256>>>(ei);
    k_scale<<<2048, 256>>>((const float4*)x);
    k_scatter<<<32768, 256>>>(ei);
    k_gemm1<<<dim3(2, 128), 256>>>(gcn_w, gcn_b);
    k_gemm2<<<dim3(1, 128), 256>>>(lin_w, lin_b, z_node);
    k_poolfused<<<N_GRAPHS, 256>>>(z_node, batch, z_graph, dec_w, dec_b);
    k_xhat<<<2048, 256>>>(batch, x_hat);
    k_ahat<<<AH_NBLK, 256, AH_SMEM>>>(z_node, a_hat);
}

// round 5
// speedup vs baseline: 2.3292x; 1.0531x over previous
#include <cuda_runtime.h>
#include <cstdint>
#include <cmath>

#define N_NODES 16384
#define N_EDGES 262144
#define N_GRAPHS 16
#define IN_CH 128
#define HID_CH 256
#define LAT 64

// ---- output layout (tuple flattened, all fp32) ----
// z_node  [16384,64]   @ 0
// z_graph [16,64]      @ 1048576
// x_hat   [16384,128]  @ 1049600
// a_hat   [16384,16384]@ 3146752

// ---- device scratch ----
__device__ float g_dinv[N_NODES];                        // degree, then rsqrt(degree)
__device__ __align__(16) float g_xs [N_NODES * IN_CH];   // dinv[r] * x[r]
__device__ __align__(16) float g_agg[N_NODES * IN_CH];   // sum incoming + self
__device__ __align__(16) float g_h  [N_NODES * HID_CH];  // relu hidden
__device__ __align__(16) float g_xg [N_GRAPHS * IN_CH];  // decoded per-graph row

// ============================================================
__global__ void k_init() {
    int i = blockIdx.x * blockDim.x + threadIdx.x;
    if (i < N_NODES) g_dinv[i] = 1.0f;               // self-loop degree
}

__global__ void k_degree(const int* __restrict__ ei) {
    int e = blockIdx.x * blockDim.x + threadIdx.x;
    if (e < N_EDGES) atomicAdd(&g_dinv[ei[N_EDGES + e]], 1.0f);
}

// d = rsqrt(deg); xs = d*x ; agg init = xs (self loop); store d back
__global__ void k_scale(const float4* __restrict__ x4) {
    int idx = blockIdx.x * blockDim.x + threadIdx.x; // < N_NODES*32
    int node = idx >> 5;
    int lane = idx & 31;
    float d = rsqrtf(g_dinv[node]);
    float4 v = x4[idx];
    v.x *= d; v.y *= d; v.z *= d; v.w *= d;
    ((float4*)g_xs)[idx] = v;
    ((float4*)g_agg)[idx] = v;
    if (lane == 0) g_dinv[node] = d;
}

// one warp per edge: 32 lanes x float4 = 128 channels; vector global atomics
__global__ void k_scatter(const int* __restrict__ ei) {
    int gid = blockIdx.x * blockDim.x + threadIdx.x;
    int e = gid >> 5;
    int lane = gid & 31;
    if (e >= N_EDGES) return;
    int r = ei[e];
    int c = ei[N_EDGES + e];
    float4 v = ((const float4*)g_xs)[r * 32 + lane];
    atomicAdd((float4*)(g_agg + c * IN_CH + lane * 4), v);
}

// ============================================================
// GEMM1: h = relu( (dinv .* agg)[16384,128] @ gcn_w[256,128]^T + gcn_b )
// ============================================================
__global__ void k_gemm1(const float* __restrict__ W, const float* __restrict__ bias) {
    __shared__ float As[128][33];
    __shared__ float Bs[128][33];
    int m0 = blockIdx.y * 128, n0 = blockIdx.x * 128;
    int tid = threadIdx.x;
    int tx = tid & 15, ty = tid >> 4;
    float acc[8][8];
#pragma unroll
    for (int i = 0; i < 8; i++)
#pragma unroll
        for (int j = 0; j < 8; j++) acc[i][j] = 0.0f;

    for (int kc = 0; kc < IN_CH; kc += 32) {
#pragma unroll
        for (int it = 0; it < 4; ++it) {
            int idx = tid + it * 256;
            int row = idx >> 3, q = idx & 7;
            float4 v = ((const float4*)g_agg)[(m0 + row) * (IN_CH / 4) + (kc >> 2) + q];
            float d = g_dinv[m0 + row];
            As[row][q * 4 + 0] = v.x * d; As[row][q * 4 + 1] = v.y * d;
            As[row][q * 4 + 2] = v.z * d; As[row][q * 4 + 3] = v.w * d;
        }
#pragma unroll
        for (int it = 0; it < 4; ++it) {
            int idx = tid + it * 256;
            int row = idx >> 3, q = idx & 7;
            float4 v = ((const float4*)W)[(n0 + row) * (IN_CH / 4) + (kc >> 2) + q];
            Bs[row][q * 4 + 0] = v.x; Bs[row][q * 4 + 1] = v.y;
            Bs[row][q * 4 + 2] = v.z; Bs[row][q * 4 + 3] = v.w;
        }
        __syncthreads();
#pragma unroll
        for (int kk = 0; kk < 32; ++kk) {
            float ra[8], rb[8];
#pragma unroll
            for (int i = 0; i < 8; i++) ra[i] = As[ty * 8 + i][kk];
#pragma unroll
            for (int j = 0; j < 8; j++) rb[j] = Bs[tx * 8 + j][kk];
#pragma unroll
            for (int i = 0; i < 8; i++)
#pragma unroll
                for (int j = 0; j < 8; j++) acc[i][j] = fmaf(ra[i], rb[j], acc[i][j]);
        }
        __syncthreads();
    }
#pragma unroll
    for (int i = 0; i < 8; i++) {
        int m = m0 + ty * 8 + i;
#pragma unroll
        for (int j = 0; j < 8; j++) {
            int n = n0 + tx * 8 + j;
            g_h[m * HID_CH + n] = fmaxf(acc[i][j] + bias[n], 0.0f);
        }
    }
}

// ============================================================
// GEMM2: z_node = h[16384,256] @ lin_w[64,256]^T + lin_b
// ============================================================
__global__ void k_gemm2(const float* __restrict__ W, const float* __restrict__ bias,
                        float* __restrict__ Z) {
    __shared__ float As[128][33];
    __shared__ float Bs[64][33];
    int m0 = blockIdx.y * 128;
    int tid = threadIdx.x;
    int tx = tid & 15, ty = tid >> 4;
    float acc[8][4];
#pragma unroll
    for (int i = 0; i < 8; i++)
#pragma unroll
        for (int j = 0; j < 4; j++) acc[i][j] = 0.0f;

    for (int kc = 0; kc < HID_CH; kc += 32) {
#pragma unroll
        for (int it = 0; it < 4; ++it) {
            int idx = tid + it * 256;
            int row = idx >> 3, q = idx & 7;
            float4 v = ((const float4*)g_h)[(m0 + row) * (HID_CH / 4) + (kc >> 2) + q];
            As[row][q * 4 + 0] = v.x; As[row][q * 4 + 1] = v.y;
            As[row][q * 4 + 2] = v.z; As[row][q * 4 + 3] = v.w;
        }
#pragma unroll
        for (int it = 0; it < 2; ++it) {
            int idx = tid + it * 256;
            int row = idx >> 3, q = idx & 7;
            float4 v = ((const float4*)W)[row * (HID_CH / 4) + (kc >> 2) + q];
            Bs[row][q * 4 + 0] = v.x; Bs[row][q * 4 + 1] = v.y;
            Bs[row][q * 4 + 2] = v.z; Bs[row][q * 4 + 3] = v.w;
        }
        __syncthreads();
#pragma unroll
        for (int kk = 0; kk < 32; ++kk) {
            float ra[8], rb[4];
#pragma unroll
            for (int i = 0; i < 8; i++) ra[i] = As[ty * 8 + i][kk];
#pragma unroll
            for (int j = 0; j < 4; j++) rb[j] = Bs[tx * 4 + j][kk];
#pragma unroll
            for (int i = 0; i < 8; i++)
#pragma unroll
                for (int j = 0; j < 4; j++) acc[i][j] = fmaf(ra[i], rb[j], acc[i][j]);
        }
        __syncthreads();
    }
#pragma unroll
    for (int i = 0; i < 8; i++) {
        int m = m0 + ty * 8 + i;
#pragma unroll
        for (int j = 0; j < 4; j++) {
            int n = tx * 4 + j;
            Z[m * LAT + n] = acc[i][j] + bias[n];
        }
    }
}

// ============================================================
// fused pool + z_graph + decoded graph rows (batch sorted -> binary search)
// ============================================================
__global__ void k_poolfused(const float* __restrict__ Z, const int* __restrict__ batch,
                            float* __restrict__ z_graph,
                            const float* __restrict__ dec_w, const float* __restrict__ dec_b) {
    __shared__ float red[4][LAT];
    __shared__ float zg[LAT];
    int g = blockIdx.x;
    int tid = threadIdx.x;
    int k = tid & 63, sub = tid >> 6;

    int lo = 0, hi = N_NODES;
    while (lo < hi) { int mid = (lo + hi) >> 1; if (batch[mid] < g) lo = mid + 1; else hi = mid; }
    int start = lo;
    hi = N_NODES;
    while (lo < hi) { int mid = (lo + hi) >> 1; if (batch[mid] < g + 1) lo = mid + 1; else hi = mid; }
    int end = lo;

    float acc = 0.0f;
    for (int n = start + sub; n < end; n += 4) acc += Z[n * LAT + k];
    red[sub][k] = acc;
    __syncthreads();
    if (sub == 0) {
        float s = red[0][k] + red[1][k] + red[2][k] + red[3][k];
        float zv = s / fmaxf((float)(end - start), 1.0f);
        z_graph[g * LAT + k] = zv;
        zg[k] = zv;
    }
    __syncthreads();
    if (tid < IN_CH) {
        float s = dec_b[tid];
#pragma unroll
        for (int kk = 0; kk < LAT; kk++) s = fmaf(zg[kk], dec_w[tid * LAT + kk], s);
        g_xg[g * IN_CH + tid] = s;
    }
}

__global__ void k_xhat(const int* __restrict__ batch, float* __restrict__ x_hat) {
    int idx = blockIdx.x * blockDim.x + threadIdx.x;  // < N_NODES*32
    int node = idx >> 5;
    int g = batch[node];
    ((float4*)x_hat)[idx] = ((const float4*)g_xg)[g * 32 + (idx & 31)];
}

// ============================================================
// a_hat = sigmoid(Z @ Z^T): symmetric, upper-tri tiles only; both output
// orientations staged through smem -> every DRAM store is a coalesced STG.128.
// tf32 mma.sync m16n8k8, block tile 128x128, 8 warps, K=64 smem-resident.
// sigmoid via tanh.approx (1 MUFU instead of 2).
// ============================================================
__device__ __forceinline__ uint32_t f2tf32(float f) {
    uint32_t u;
    asm("cvt.rna.tf32.f32 %0, %1;" : "=r"(u) : "f"(f));
    return u;
}
__device__ __forceinline__ float fsig(float x) {
    float t;
    asm("tanh.approx.f32 %0, %1;" : "=f"(t) : "f"(x * 0.5f));
    return fmaf(t, 0.5f, 0.5f);
}

#define AH_LD 68          // tf32 tile pitch (uint32)
#define AH_TLD 132        // staging pitch (float): STS patterns conflict-free-ish
#define AH_NTILE 128
#define AH_NBLK (AH_NTILE * (AH_NTILE + 1) / 2)   // 8256

__global__ __launch_bounds__(256, 2) void k_ahat(const float* __restrict__ Z,
                                                 float* __restrict__ out) {
    extern __shared__ uint32_t smbuf[];
    uint32_t* As = smbuf;                 // [128][AH_LD]
    uint32_t* Bs = smbuf + 128 * AH_LD;   // [128][AH_LD]

    // decode linear block -> (bm<=bn): L = bn*(bn+1)/2 + bm   (float sqrt + fixup)
    int L = blockIdx.x;
    int bn = (int)((sqrtf(8.0f * (float)L + 1.0f) - 1.0f) * 0.5f);
    while ((bn + 1) * (bn + 2) / 2 <= L) bn++;
    while (bn * (bn + 1) / 2 > L) bn--;
    int bm = L - bn * (bn + 1) / 2;

    int tid = threadIdx.x;
    const float4* Z4 = (const float4*)Z;

#pragma unroll
    for (int it = 0; it < 8; ++it) {
        int idx = tid + it * 256;       // 2048 float4 per tile
        int row = idx >> 4, q = idx & 15;
        float4 va = Z4[(bm * 128 + row) * 16 + q];
        As[row * AH_LD + q * 4 + 0] = f2tf32(va.x);
        As[row * AH_LD + q * 4 + 1] = f2tf32(va.y);
        As[row * AH_LD + q * 4 + 2] = f2tf32(va.z);
        As[row * AH_LD + q * 4 + 3] = f2tf32(va.w);
        float4 vb = Z4[(bn * 128 + row) * 16 + q];
        Bs[row * AH_LD + q * 4 + 0] = f2tf32(vb.x);
        Bs[row * AH_LD + q * 4 + 1] = f2tf32(vb.y);
        Bs[row * AH_LD + q * 4 + 2] = f2tf32(vb.z);
        Bs[row * AH_LD + q * 4 + 3] = f2tf32(vb.w);
    }
    __syncthreads();

    int warp = tid >> 5, lane = tid & 31;
    int wm = (warp >> 2) * 64;
    int wn = (warp & 3) * 32;
    int gp = lane >> 2, tq = lane & 3;

    float acc[4][4][4];
#pragma unroll
    for (int mt = 0; mt < 4; mt++)
#pragma unroll
        for (int nt = 0; nt < 4; nt++)
#pragma unroll
            for (int r = 0; r < 4; r++) acc[mt][nt][r] = 0.0f;

#pragma unroll
    for (int ks = 0; ks < 8; ++ks) {
        int kb = ks * 8;
        uint32_t a[4][4], b[4][2];
#pragma unroll
        for (int mt = 0; mt < 4; ++mt) {
            int r0 = wm + mt * 16 + gp;
            a[mt][0] = As[r0 * AH_LD + kb + tq];
            a[mt][1] = As[(r0 + 8) * AH_LD + kb + tq];
            a[mt][2] = As[r0 * AH_LD + kb + tq + 4];
            a[mt][3] = As[(r0 + 8) * AH_LD + kb + tq + 4];
        }
#pragma unroll
        for (int nt = 0; nt < 4; ++nt) {
            int c0 = wn + nt * 8 + gp;
            b[nt][0] = Bs[c0 * AH_LD + kb + tq];
            b[nt][1] = Bs[c0 * AH_LD + kb + tq + 4];
        }
#pragma unroll
        for (int mt = 0; mt < 4; ++mt)
#pragma unroll
            for (int nt = 0; nt < 4; ++nt) {
                asm volatile(
                    "mma.sync.aligned.m16n8k8.row.col.f32.tf32.tf32.f32 "
                    "{%0,%1,%2,%3}, {%4,%5,%6,%7}, {%8,%9}, {%0,%1,%2,%3};"
                    : "+f"(acc[mt][nt][0]), "+f"(acc[mt][nt][1]),
                      "+f"(acc[mt][nt][2]), "+f"(acc[mt][nt][3])
                    : "r"(a[mt][0]), "r"(a[mt][1]), "r"(a[mt][2]), "r"(a[mt][3]),
                      "r"(b[nt][0]), "r"(b[nt][1]));
            }
    }

    // sigmoid in registers
#pragma unroll
    for (int mt = 0; mt < 4; ++mt)
#pragma unroll
        for (int nt = 0; nt < 4; ++nt)
#pragma unroll
            for (int r = 0; r < 4; ++r) acc[mt][nt][r] = fsig(acc[mt][nt][r]);

    float* S = (float*)smbuf;   // [128][AH_TLD] staging, 67584 B

    // pass 1: direct orientation -> coalesced STG.128 to (bm,bn)
    __syncthreads();            // all As/Bs reads done before overwrite
#pragma unroll
    for (int mt = 0; mt < 4; ++mt)
#pragma unroll
        for (int nt = 0; nt < 4; ++nt) {
            int rl = wm + mt * 16 + gp;
            int cl = wn + nt * 8 + tq * 2;
            *(float2*)(S + rl * AH_TLD + cl)       = make_float2(acc[mt][nt][0], acc[mt][nt][1]);
            *(float2*)(S + (rl + 8) * AH_TLD + cl) = make_float2(acc[mt][nt][2], acc[mt][nt][3]);
        }
    __syncthreads();
#pragma unroll
    for (int it = 0; it < 16; ++it) {
        int idx = tid + it * 256;     // 4096 float4
        int rt = idx >> 5, q = idx & 31;
        float4 w = *(const float4*)(S + rt * AH_TLD + q * 4);
        *(float4*)(out + (size_t)(bm * 128 + rt) * N_NODES + bn * 128 + q * 4) = w;
    }

    // pass 2 (off-diag): transposed orientation -> coalesced STG.128 to (bn,bm)
    if (bm != bn) {
        __syncthreads();
#pragma unroll
        for (int mt = 0; mt < 4; ++mt)
#pragma unroll
            for (int nt = 0; nt < 4; ++nt) {
                int rl = wm + mt * 16 + gp;
                int cl = wn + nt * 8 + tq * 2;
                S[cl * AH_TLD + rl]           = acc[mt][nt][0];
                S[(cl + 1) * AH_TLD + rl]     = acc[mt][nt][1];
                S[cl * AH_TLD + rl + 8]       = acc[mt][nt][2];
                S[(cl + 1) * AH_TLD + rl + 8] = acc[mt][nt][3];
            }
        __syncthreads();
#pragma unroll
        for (int it = 0; it < 16; ++it) {
            int idx = tid + it * 256;
            int rt = idx >> 5, q = idx & 31;
            float4 w = *(const float4*)(S + rt * AH_TLD + q * 4);
            *(float4*)(out + (size_t)(bn * 128 + rt) * N_NODES + bm * 128 + q * 4) = w;
        }
    }
}

// ============================================================
// launch
// ============================================================
extern "C" void kernel_launch(void* const* d_in, const int* in_sizes, int n_in,
                              void* d_out, int out_size) {
    const float* x     = (const float*)d_in[0];
    const int*   ei    = (const int*)d_in[1];    // int32
    const int*   batch = (const int*)d_in[2];    // int32, sorted
    const float* gcn_w = (const float*)d_in[3];
    const float* gcn_b = (const float*)d_in[4];
    const float* lin_w = (const float*)d_in[5];
    const float* lin_b = (const float*)d_in[6];
    const float* dec_w = (const float*)d_in[7];
    const float* dec_b = (const float*)d_in[8];

    float* out     = (float*)d_out;
    float* z_node  = out;
    float* z_graph = out + 1048576;
    float* x_hat   = out + 1049600;
    float* a_hat   = out + 3146752;

    const int AH_SMEM = 2 * 128 * AH_LD * 4;  // 69632 B
    cudaFuncSetAttribute(k_ahat, cudaFuncAttributeMaxDynamicSharedMemorySize, AH_SMEM);

    k_init<<<64, 256>>>();
    k_degree<<<1024, 256>>>(ei);
    k_scale<<<2048, 256>>>((const float4*)x);
    k_scatter<<<32768, 256>>>(ei);
    k_gemm1<<<dim3(2, 128), 256>>>(gcn_w, gcn_b);
    k_gemm2<<<dim3(1, 128), 256>>>(lin_w, lin_b, z_node);
    k_poolfused<<<N_GRAPHS, 256>>>(z_node, batch, z_graph, dec_w, dec_b);
    k_xhat<<<2048, 256>>>(batch, x_hat);
    k_ahat<<<AH_NBLK, 256, AH_SMEM>>>(z_node, a_hat);
}

// round 6
// speedup vs baseline: 2.4061x; 1.0330x over previous
#include <cuda_runtime.h>
#include <cstdint>
#include <cmath>

#define N_NODES 16384
#define N_EDGES 262144
#define N_GRAPHS 16
#define IN_CH 128
#define HID_CH 256
#define LAT 64

// ---- output layout (tuple flattened, all fp32) ----
// z_node  [16384,64]   @ 0
// z_graph [16,64]      @ 1048576
// x_hat   [16384,128]  @ 1049600
// a_hat   [16384,16384]@ 3146752

// ---- device scratch ----
__device__ float g_dinv[N_NODES];                        // degree, then rsqrt(degree)
__device__ __align__(16) float g_xs [N_NODES * IN_CH];   // dinv[r] * x[r]
__device__ __align__(16) float g_agg[N_NODES * IN_CH];   // sum incoming + self
__device__ __align__(16) float g_h  [N_NODES * HID_CH];  // relu hidden
__device__ __align__(16) float g_xg [N_GRAPHS * IN_CH];  // decoded per-graph row

// ============================================================
__global__ void k_init() {
    int i = blockIdx.x * blockDim.x + threadIdx.x;
    if (i < N_NODES) g_dinv[i] = 1.0f;               // self-loop degree
}

__global__ void k_degree(const int* __restrict__ ei) {
    int e = blockIdx.x * blockDim.x + threadIdx.x;
    if (e < N_EDGES) atomicAdd(&g_dinv[ei[N_EDGES + e]], 1.0f);
}

// d = rsqrt(deg); xs = d*x ; agg init = xs (self loop); store d back
__global__ void k_scale(const float4* __restrict__ x4) {
    int idx = blockIdx.x * blockDim.x + threadIdx.x; // < N_NODES*32
    int node = idx >> 5;
    int lane = idx & 31;
    float d = rsqrtf(g_dinv[node]);
    float4 v = x4[idx];
    v.x *= d; v.y *= d; v.z *= d; v.w *= d;
    ((float4*)g_xs)[idx] = v;
    ((float4*)g_agg)[idx] = v;
    if (lane == 0) g_dinv[node] = d;
}

// one warp per edge: 32 lanes x float4 = 128 channels; vector global atomics
__global__ void k_scatter(const int* __restrict__ ei) {
    int gid = blockIdx.x * blockDim.x + threadIdx.x;
    int e = gid >> 5;
    int lane = gid & 31;
    if (e >= N_EDGES) return;
    int r = ei[e];
    int c = ei[N_EDGES + e];
    float4 v = ((const float4*)g_xs)[r * 32 + lane];
    atomicAdd((float4*)(g_agg + c * IN_CH + lane * 4), v);
}

// ============================================================
// GEMM1: h = relu( (dinv .* agg)[16384,128] @ gcn_w[256,128]^T + gcn_b )
// k-major smem tiles -> LDS.128 operand loads in the hot loop
// ============================================================
__global__ void k_gemm1(const float* __restrict__ W, const float* __restrict__ bias) {
    __shared__ float As[32][132];
    __shared__ float Bs[32][132];
    int m0 = blockIdx.y * 128, n0 = blockIdx.x * 128;
    int tid = threadIdx.x;
    int tx = tid & 15, ty = tid >> 4;
    float acc[8][8];
#pragma unroll
    for (int i = 0; i < 8; i++)
#pragma unroll
        for (int j = 0; j < 8; j++) acc[i][j] = 0.0f;

    for (int kc = 0; kc < IN_CH; kc += 32) {
#pragma unroll
        for (int it = 0; it < 4; ++it) {
            int idx = tid + it * 256;  // 1024 float4 in 128x32 tile
            int row = idx >> 3, q = idx & 7;
            float4 v = ((const float4*)g_agg)[(m0 + row) * (IN_CH / 4) + (kc >> 2) + q];
            float d = g_dinv[m0 + row];
            As[q * 4 + 0][row] = v.x * d; As[q * 4 + 1][row] = v.y * d;
            As[q * 4 + 2][row] = v.z * d; As[q * 4 + 3][row] = v.w * d;
        }
#pragma unroll
        for (int it = 0; it < 4; ++it) {
            int idx = tid + it * 256;
            int row = idx >> 3, q = idx & 7;
            float4 v = ((const float4*)W)[(n0 + row) * (IN_CH / 4) + (kc >> 2) + q];
            Bs[q * 4 + 0][row] = v.x; Bs[q * 4 + 1][row] = v.y;
            Bs[q * 4 + 2][row] = v.z; Bs[q * 4 + 3][row] = v.w;
        }
        __syncthreads();
#pragma unroll
        for (int kk = 0; kk < 32; ++kk) {
            float4 a0 = *(const float4*)&As[kk][ty * 8];
            float4 a1 = *(const float4*)&As[kk][ty * 8 + 4];
            float4 b0 = *(const float4*)&Bs[kk][tx * 8];
            float4 b1 = *(const float4*)&Bs[kk][tx * 8 + 4];
            float ra[8] = {a0.x, a0.y, a0.z, a0.w, a1.x, a1.y, a1.z, a1.w};
            float rb[8] = {b0.x, b0.y, b0.z, b0.w, b1.x, b1.y, b1.z, b1.w};
#pragma unroll
            for (int i = 0; i < 8; i++)
#pragma unroll
                for (int j = 0; j < 8; j++) acc[i][j] = fmaf(ra[i], rb[j], acc[i][j]);
        }
        __syncthreads();
    }
#pragma unroll
    for (int i = 0; i < 8; i++) {
        int m = m0 + ty * 8 + i;
#pragma unroll
        for (int j = 0; j < 8; j++) {
            int n = n0 + tx * 8 + j;
            g_h[m * HID_CH + n] = fmaxf(acc[i][j] + bias[n], 0.0f);
        }
    }
}

// ============================================================
// GEMM2: z_node = h[16384,256] @ lin_w[64,256]^T + lin_b   (k-major tiles)
// ============================================================
__global__ void k_gemm2(const float* __restrict__ W, const float* __restrict__ bias,
                        float* __restrict__ Z) {
    __shared__ float As[32][132];
    __shared__ float Bs[32][68];
    int m0 = blockIdx.y * 128;
    int tid = threadIdx.x;
    int tx = tid & 15, ty = tid >> 4;
    float acc[8][4];
#pragma unroll
    for (int i = 0; i < 8; i++)
#pragma unroll
        for (int j = 0; j < 4; j++) acc[i][j] = 0.0f;

    for (int kc = 0; kc < HID_CH; kc += 32) {
#pragma unroll
        for (int it = 0; it < 4; ++it) {
            int idx = tid + it * 256;
            int row = idx >> 3, q = idx & 7;
            float4 v = ((const float4*)g_h)[(m0 + row) * (HID_CH / 4) + (kc >> 2) + q];
            As[q * 4 + 0][row] = v.x; As[q * 4 + 1][row] = v.y;
            As[q * 4 + 2][row] = v.z; As[q * 4 + 3][row] = v.w;
        }
#pragma unroll
        for (int it = 0; it < 2; ++it) {
            int idx = tid + it * 256;  // 512 float4 in 64x32 tile
            int row = idx >> 3, q = idx & 7;
            float4 v = ((const float4*)W)[row * (HID_CH / 4) + (kc >> 2) + q];
            Bs[q * 4 + 0][row] = v.x; Bs[q * 4 + 1][row] = v.y;
            Bs[q * 4 + 2][row] = v.z; Bs[q * 4 + 3][row] = v.w;
        }
        __syncthreads();
#pragma unroll
        for (int kk = 0; kk < 32; ++kk) {
            float4 a0 = *(const float4*)&As[kk][ty * 8];
            float4 a1 = *(const float4*)&As[kk][ty * 8 + 4];
            float4 b0 = *(const float4*)&Bs[kk][tx * 4];
            float ra[8] = {a0.x, a0.y, a0.z, a0.w, a1.x, a1.y, a1.z, a1.w};
            float rb[4] = {b0.x, b0.y, b0.z, b0.w};
#pragma unroll
            for (int i = 0; i < 8; i++)
#pragma unroll
                for (int j = 0; j < 4; j++) acc[i][j] = fmaf(ra[i], rb[j], acc[i][j]);
        }
        __syncthreads();
    }
#pragma unroll
    for (int i = 0; i < 8; i++) {
        int m = m0 + ty * 8 + i;
#pragma unroll
        for (int j = 0; j < 4; j++) {
            int n = tx * 4 + j;
            Z[m * LAT + n] = acc[i][j] + bias[n];
        }
    }
}

// ============================================================
// fused pool + z_graph + decoded graph rows (batch sorted -> binary search)
// ============================================================
__global__ void k_poolfused(const float* __restrict__ Z, const int* __restrict__ batch,
                            float* __restrict__ z_graph,
                            const float* __restrict__ dec_w, const float* __restrict__ dec_b) {
    __shared__ float red[4][LAT];
    __shared__ float zg[LAT];
    int g = blockIdx.x;
    int tid = threadIdx.x;
    int k = tid & 63, sub = tid >> 6;

    int lo = 0, hi = N_NODES;
    while (lo < hi) { int mid = (lo + hi) >> 1; if (batch[mid] < g) lo = mid + 1; else hi = mid; }
    int start = lo;
    hi = N_NODES;
    while (lo < hi) { int mid = (lo + hi) >> 1; if (batch[mid] < g + 1) lo = mid + 1; else hi = mid; }
    int end = lo;

    float acc = 0.0f;
    for (int n = start + sub; n < end; n += 4) acc += Z[n * LAT + k];
    red[sub][k] = acc;
    __syncthreads();
    if (sub == 0) {
        float s = red[0][k] + red[1][k] + red[2][k] + red[3][k];
        float zv = s / fmaxf((float)(end - start), 1.0f);
        z_graph[g * LAT + k] = zv;
        zg[k] = zv;
    }
    __syncthreads();
    if (tid < IN_CH) {
        float s = dec_b[tid];
#pragma unroll
        for (int kk = 0; kk < LAT; kk++) s = fmaf(zg[kk], dec_w[tid * LAT + kk], s);
        g_xg[g * IN_CH + tid] = s;
    }
}

__global__ void k_xhat(const int* __restrict__ batch, float* __restrict__ x_hat) {
    int idx = blockIdx.x * blockDim.x + threadIdx.x;  // < N_NODES*32
    int node = idx >> 5;
    int g = batch[node];
    ((float4*)x_hat)[idx] = ((const float4*)g_xg)[g * 32 + (idx & 31)];
}

// ============================================================
// a_hat = sigmoid(Z @ Z^T): symmetric, upper-tri tiles only.
// Direct orientation: STG.64 straight from registers (full 32B sectors).
// Mirror orientation: smem transpose -> coalesced STG.128.
// tf32 mma.sync m16n8k8, block 128x128, 8 warps, K=64 resident.
// ============================================================
__device__ __forceinline__ uint32_t f2tf32(float f) {
    uint32_t u;
    asm("cvt.rna.tf32.f32 %0, %1;" : "=r"(u) : "f"(f));
    return u;
}
__device__ __forceinline__ float fsig(float x) {
    float t;
    asm("tanh.approx.f32 %0, %1;" : "=f"(t) : "f"(x * 0.5f));
    return fmaf(t, 0.5f, 0.5f);
}

#define AH_LD 68          // tf32 tile pitch (uint32)
#define AH_TLD 132        // transpose staging pitch (float)
#define AH_NTILE 128
#define AH_NBLK (AH_NTILE * (AH_NTILE + 1) / 2)   // 8256

__global__ __launch_bounds__(256, 2) void k_ahat(const float* __restrict__ Z,
                                                 float* __restrict__ out) {
    extern __shared__ uint32_t smbuf[];
    uint32_t* As = smbuf;                 // [128][AH_LD]
    uint32_t* Bs = smbuf + 128 * AH_LD;   // [128][AH_LD]

    // decode linear block -> (bm<=bn): L = bn*(bn+1)/2 + bm
    int L = blockIdx.x;
    int bn = (int)((sqrtf(8.0f * (float)L + 1.0f) - 1.0f) * 0.5f);
    while ((bn + 1) * (bn + 2) / 2 <= L) bn++;
    while (bn * (bn + 1) / 2 > L) bn--;
    int bm = L - bn * (bn + 1) / 2;

    int tid = threadIdx.x;
    const float4* Z4 = (const float4*)Z;

#pragma unroll
    for (int it = 0; it < 8; ++it) {
        int idx = tid + it * 256;       // 2048 float4 per tile
        int row = idx >> 4, q = idx & 15;
        float4 va = Z4[(bm * 128 + row) * 16 + q];
        As[row * AH_LD + q * 4 + 0] = f2tf32(va.x);
        As[row * AH_LD + q * 4 + 1] = f2tf32(va.y);
        As[row * AH_LD + q * 4 + 2] = f2tf32(va.z);
        As[row * AH_LD + q * 4 + 3] = f2tf32(va.w);
        float4 vb = Z4[(bn * 128 + row) * 16 + q];
        Bs[row * AH_LD + q * 4 + 0] = f2tf32(vb.x);
        Bs[row * AH_LD + q * 4 + 1] = f2tf32(vb.y);
        Bs[row * AH_LD + q * 4 + 2] = f2tf32(vb.z);
        Bs[row * AH_LD + q * 4 + 3] = f2tf32(vb.w);
    }
    __syncthreads();

    int warp = tid >> 5, lane = tid & 31;
    int wm = (warp >> 2) * 64;
    int wn = (warp & 3) * 32;
    int gp = lane >> 2, tq = lane & 3;

    float acc[4][4][4];
#pragma unroll
    for (int mt = 0; mt < 4; mt++)
#pragma unroll
        for (int nt = 0; nt < 4; nt++)
#pragma unroll
            for (int r = 0; r < 4; r++) acc[mt][nt][r] = 0.0f;

#pragma unroll
    for (int ks = 0; ks < 8; ++ks) {
        int kb = ks * 8;
        uint32_t a[4][4], b[4][2];
#pragma unroll
        for (int mt = 0; mt < 4; ++mt) {
            int r0 = wm + mt * 16 + gp;
            a[mt][0] = As[r0 * AH_LD + kb + tq];
            a[mt][1] = As[(r0 + 8) * AH_LD + kb + tq];
            a[mt][2] = As[r0 * AH_LD + kb + tq + 4];
            a[mt][3] = As[(r0 + 8) * AH_LD + kb + tq + 4];
        }
#pragma unroll
        for (int nt = 0; nt < 4; ++nt) {
            int c0 = wn + nt * 8 + gp;
            b[nt][0] = Bs[c0 * AH_LD + kb + tq];
            b[nt][1] = Bs[c0 * AH_LD + kb + tq + 4];
        }
#pragma unroll
        for (int mt = 0; mt < 4; ++mt)
#pragma unroll
            for (int nt = 0; nt < 4; ++nt) {
                asm volatile(
                    "mma.sync.aligned.m16n8k8.row.col.f32.tf32.tf32.f32 "
                    "{%0,%1,%2,%3}, {%4,%5,%6,%7}, {%8,%9}, {%0,%1,%2,%3};"
                    : "+f"(acc[mt][nt][0]), "+f"(acc[mt][nt][1]),
                      "+f"(acc[mt][nt][2]), "+f"(acc[mt][nt][3])
                    : "r"(a[mt][0]), "r"(a[mt][1]), "r"(a[mt][2]), "r"(a[mt][3]),
                      "r"(b[nt][0]), "r"(b[nt][1]));
            }
    }

    // sigmoid in registers, direct STG.64 store of (bm,bn) tile
#pragma unroll
    for (int mt = 0; mt < 4; ++mt)
#pragma unroll
        for (int nt = 0; nt < 4; ++nt) {
#pragma unroll
            for (int r = 0; r < 4; ++r) acc[mt][nt][r] = fsig(acc[mt][nt][r]);
            int row = bm * 128 + wm + mt * 16 + gp;
            int col = bn * 128 + wn + nt * 8 + tq * 2;
            *(float2*)(out + (size_t)row * N_NODES + col) =
                make_float2(acc[mt][nt][0], acc[mt][nt][1]);
            *(float2*)(out + (size_t)(row + 8) * N_NODES + col) =
                make_float2(acc[mt][nt][2], acc[mt][nt][3]);
        }

    // mirror tile: transpose through smem (reuse As/Bs), coalesced STG.128
    if (bm != bn) {
        __syncthreads();                  // As/Bs reads all done
        float* S = (float*)smbuf;         // [128][AH_TLD], 67584 B
#pragma unroll
        for (int mt = 0; mt < 4; ++mt)
#pragma unroll
            for (int nt = 0; nt < 4; ++nt) {
                int rl = wm + mt * 16 + gp;
                int cl = wn + nt * 8 + tq * 2;
                S[cl * AH_TLD + rl]           = acc[mt][nt][0];
                S[(cl + 1) * AH_TLD + rl]     = acc[mt][nt][1];
                S[cl * AH_TLD + rl + 8]       = acc[mt][nt][2];
                S[(cl + 1) * AH_TLD + rl + 8] = acc[mt][nt][3];
            }
        __syncthreads();
#pragma unroll
        for (int it = 0; it < 16; ++it) {
            int idx = tid + it * 256;     // 4096 float4
            int rt = idx >> 5, q = idx & 31;
            float4 w = *(const float4*)(S + rt * AH_TLD + q * 4);
            *(float4*)(out + (size_t)(bn * 128 + rt) * N_NODES + bm * 128 + q * 4) = w;
        }
    }
}

// ============================================================
// launch
// ============================================================
extern "C" void kernel_launch(void* const* d_in, const int* in_sizes, int n_in,
                              void* d_out, int out_size) {
    const float* x     = (const float*)d_in[0];
    const int*   ei    = (const int*)d_in[1];    // int32
    const int*   batch = (const int*)d_in[2];    // int32, sorted
    const float* gcn_w = (const float*)d_in[3];
    const float* gcn_b = (const float*)d_in[4];
    const float* lin_w = (const float*)d_in[5];
    const float* lin_b = (const float*)d_in[6];
    const float* dec_w = (const float*)d_in[7];
    const float* dec_b = (const float*)d_in[8];

    float* out     = (float*)d_out;
    float* z_node  = out;
    float* z_graph = out + 1048576;
    float* x_hat   = out + 1049600;
    float* a_hat   = out + 3146752;

    const int AH_SMEM = 2 * 128 * AH_LD * 4;  // 69632 B
    cudaFuncSetAttribute(k_ahat, cudaFuncAttributeMaxDynamicSharedMemorySize, AH_SMEM);

    k_init<<<64, 256>>>();
    k_degree<<<1024, 256>>>(ei);
    k_scale<<<2048, 256>>>((const float4*)x);
    k_scatter<<<32768, 256>>>(ei);
    k_gemm1<<<dim3(2, 128), 256>>>(gcn_w, gcn_b);
    k_gemm2<<<dim3(1, 128), 256>>>(lin_w, lin_b, z_node);
    k_poolfused<<<N_GRAPHS, 256>>>(z_node, batch, z_graph, dec_w, dec_b);
    k_xhat<<<2048, 256>>>(batch, x_hat);
    k_ahat<<<AH_NBLK, 256, AH_SMEM>>>(z_node, a_hat);
}

// round 7
// speedup vs baseline: 2.6949x; 1.1201x over previous
#include <cuda_runtime.h>
#include <cstdint>
#include <cmath>

#define N_NODES 16384
#define N_EDGES 262144
#define N_GRAPHS 16
#define IN_CH 128
#define HID_CH 256
#define LAT 64

// ---- output layout (tuple flattened, all fp32) ----
// z_node  [16384,64]   @ 0
// z_graph [16,64]      @ 1048576
// x_hat   [16384,128]  @ 1049600
// a_hat   [16384,16384]@ 3146752

// ---- device scratch ----
__device__ float g_dinv[N_NODES];                        // degree, then rsqrt(degree)
__device__ __align__(16) float g_xs [N_NODES * IN_CH];   // dinv[r] * x[r]
__device__ __align__(16) float g_agg[N_NODES * IN_CH];   // sum incoming + self
__device__ __align__(16) float g_h  [N_NODES * HID_CH];  // relu hidden
__device__ __align__(16) float g_xg [N_GRAPHS * IN_CH];  // decoded per-graph row

__device__ __forceinline__ uint32_t f2tf32(float f) {
    uint32_t u;
    asm("cvt.rna.tf32.f32 %0, %1;" : "=r"(u) : "f"(f));
    return u;
}
__device__ __forceinline__ float fsig(float x) {
    float t;
    asm("tanh.approx.f32 %0, %1;" : "=f"(t) : "f"(x * 0.5f));
    return fmaf(t, 0.5f, 0.5f);
}
#define MMA_TF32(acc, a, b)                                                    \
    asm volatile(                                                              \
        "mma.sync.aligned.m16n8k8.row.col.f32.tf32.tf32.f32 "                  \
        "{%0,%1,%2,%3}, {%4,%5,%6,%7}, {%8,%9}, {%0,%1,%2,%3};"                \
        : "+f"(acc[0]), "+f"(acc[1]), "+f"(acc[2]), "+f"(acc[3])               \
        : "r"(a[0]), "r"(a[1]), "r"(a[2]), "r"(a[3]), "r"(b[0]), "r"(b[1]))

#define TLD 68   // tf32 smem pitch (uint32)

// ============================================================
__global__ void k_init() {
    int i = blockIdx.x * blockDim.x + threadIdx.x;
    if (i < N_NODES) g_dinv[i] = 1.0f;               // self-loop degree
}

__global__ void k_degree(const int* __restrict__ ei) {
    int e = blockIdx.x * blockDim.x + threadIdx.x;
    if (e < N_EDGES) atomicAdd(&g_dinv[ei[N_EDGES + e]], 1.0f);
}

// d = rsqrt(deg); xs = d*x ; agg init = xs (self loop); store d back
__global__ void k_scale(const float4* __restrict__ x4) {
    int idx = blockIdx.x * blockDim.x + threadIdx.x; // < N_NODES*32
    int node = idx >> 5;
    int lane = idx & 31;
    float d = rsqrtf(g_dinv[node]);
    float4 v = x4[idx];
    v.x *= d; v.y *= d; v.z *= d; v.w *= d;
    ((float4*)g_xs)[idx] = v;
    ((float4*)g_agg)[idx] = v;
    if (lane == 0) g_dinv[node] = d;
}

// one warp per edge: 32 lanes x float4 = 128 channels; vector global atomics
__global__ void k_scatter(const int* __restrict__ ei) {
    int gid = blockIdx.x * blockDim.x + threadIdx.x;
    int e = gid >> 5;
    int lane = gid & 31;
    if (e >= N_EDGES) return;
    int r = ei[e];
    int c = ei[N_EDGES + e];
    float4 v = ((const float4*)g_xs)[r * 32 + lane];
    atomicAdd((float4*)(g_agg + c * IN_CH + lane * 4), v);
}

// ============================================================
// GEMM1 (tf32 MMA): h = relu( (dinv.*agg)[16384,128] @ gcn_w[256,128]^T + b )
// block 128x128, 8 warps (2x4), warp 64x32, K chunked 64 (2 chunks)
// ============================================================
__global__ __launch_bounds__(256, 2) void k_gemm1(const float* __restrict__ W,
                                                  const float* __restrict__ bias) {
    extern __shared__ uint32_t smbuf[];
    uint32_t* As = smbuf;               // [128][TLD]
    uint32_t* Bs = smbuf + 128 * TLD;   // [128][TLD]
    int m0 = blockIdx.y * 128, n0 = blockIdx.x * 128;
    int tid = threadIdx.x;
    int warp = tid >> 5, lane = tid & 31;
    int wm = (warp >> 2) * 64, wn = (warp & 3) * 32;
    int gp = lane >> 2, tq = lane & 3;

    float acc[4][4][4];
#pragma unroll
    for (int mt = 0; mt < 4; mt++)
#pragma unroll
        for (int nt = 0; nt < 4; nt++)
#pragma unroll
            for (int r = 0; r < 4; r++) acc[mt][nt][r] = 0.0f;

#pragma unroll
    for (int kc = 0; kc < IN_CH; kc += 64) {
        if (kc) __syncthreads();
#pragma unroll
        for (int it = 0; it < 8; ++it) {
            int idx = tid + it * 256;       // 2048 float4 per 128x64 tile
            int row = idx >> 4, q = idx & 15;
            float4 va = ((const float4*)g_agg)[(m0 + row) * (IN_CH / 4) + (kc >> 2) + q];
            float d = g_dinv[m0 + row];
            As[row * TLD + q * 4 + 0] = f2tf32(va.x * d);
            As[row * TLD + q * 4 + 1] = f2tf32(va.y * d);
            As[row * TLD + q * 4 + 2] = f2tf32(va.z * d);
            As[row * TLD + q * 4 + 3] = f2tf32(va.w * d);
            float4 vb = ((const float4*)W)[(n0 + row) * (IN_CH / 4) + (kc >> 2) + q];
            Bs[row * TLD + q * 4 + 0] = f2tf32(vb.x);
            Bs[row * TLD + q * 4 + 1] = f2tf32(vb.y);
            Bs[row * TLD + q * 4 + 2] = f2tf32(vb.z);
            Bs[row * TLD + q * 4 + 3] = f2tf32(vb.w);
        }
        __syncthreads();
#pragma unroll
        for (int ks = 0; ks < 8; ++ks) {
            int kb = ks * 8;
            uint32_t a[4][4], b[4][2];
#pragma unroll
            for (int mt = 0; mt < 4; ++mt) {
                int r0 = wm + mt * 16 + gp;
                a[mt][0] = As[r0 * TLD + kb + tq];
                a[mt][1] = As[(r0 + 8) * TLD + kb + tq];
                a[mt][2] = As[r0 * TLD + kb + tq + 4];
                a[mt][3] = As[(r0 + 8) * TLD + kb + tq + 4];
            }
#pragma unroll
            for (int nt = 0; nt < 4; ++nt) {
                int c0 = wn + nt * 8 + gp;
                b[nt][0] = Bs[c0 * TLD + kb + tq];
                b[nt][1] = Bs[c0 * TLD + kb + tq + 4];
            }
#pragma unroll
            for (int mt = 0; mt < 4; ++mt)
#pragma unroll
                for (int nt = 0; nt < 4; ++nt) MMA_TF32(acc[mt][nt], a[mt], b[nt]);
        }
    }

#pragma unroll
    for (int mt = 0; mt < 4; ++mt)
#pragma unroll
        for (int nt = 0; nt < 4; ++nt) {
            int row = m0 + wm + mt * 16 + gp;
            int col = n0 + wn + nt * 8 + tq * 2;
            float b0 = bias[col], b1 = bias[col + 1];
            *(float2*)(g_h + row * HID_CH + col) =
                make_float2(fmaxf(acc[mt][nt][0] + b0, 0.0f), fmaxf(acc[mt][nt][1] + b1, 0.0f));
            *(float2*)(g_h + (row + 8) * HID_CH + col) =
                make_float2(fmaxf(acc[mt][nt][2] + b0, 0.0f), fmaxf(acc[mt][nt][3] + b1, 0.0f));
        }
}

// ============================================================
// GEMM2 (tf32 MMA): z_node = h[16384,256] @ lin_w[64,256]^T + lin_b
// block 128x64, 8 warps (4x2), warp 32x32, K chunked 64 (4 chunks)
// ============================================================
__global__ __launch_bounds__(256) void k_gemm2(const float* __restrict__ W,
                                               const float* __restrict__ bias,
                                               float* __restrict__ Z) {
    extern __shared__ uint32_t smbuf[];
    uint32_t* As = smbuf;               // [128][TLD]
    uint32_t* Bs = smbuf + 128 * TLD;   // [64][TLD]
    int m0 = blockIdx.x * 128;
    int tid = threadIdx.x;
    int warp = tid >> 5, lane = tid & 31;
    int wm = (warp >> 1) * 32, wn = (warp & 1) * 32;
    int gp = lane >> 2, tq = lane & 3;

    float acc[2][4][4];
#pragma unroll
    for (int mt = 0; mt < 2; mt++)
#pragma unroll
        for (int nt = 0; nt < 4; nt++)
#pragma unroll
            for (int r = 0; r < 4; r++) acc[mt][nt][r] = 0.0f;

#pragma unroll
    for (int kc = 0; kc < HID_CH; kc += 64) {
        if (kc) __syncthreads();
#pragma unroll
        for (int it = 0; it < 8; ++it) {
            int idx = tid + it * 256;       // A: 2048 float4
            int row = idx >> 4, q = idx & 15;
            float4 va = ((const float4*)g_h)[(m0 + row) * (HID_CH / 4) + (kc >> 2) + q];
            As[row * TLD + q * 4 + 0] = f2tf32(va.x);
            As[row * TLD + q * 4 + 1] = f2tf32(va.y);
            As[row * TLD + q * 4 + 2] = f2tf32(va.z);
            As[row * TLD + q * 4 + 3] = f2tf32(va.w);
        }
#pragma unroll
        for (int it = 0; it < 4; ++it) {
            int idx = tid + it * 256;       // B: 1024 float4
            int row = idx >> 4, q = idx & 15;
            float4 vb = ((const float4*)W)[row * (HID_CH / 4) + (kc >> 2) + q];
            Bs[row * TLD + q * 4 + 0] = f2tf32(vb.x);
            Bs[row * TLD + q * 4 + 1] = f2tf32(vb.y);
            Bs[row * TLD + q * 4 + 2] = f2tf32(vb.z);
            Bs[row * TLD + q * 4 + 3] = f2tf32(vb.w);
        }
        __syncthreads();
#pragma unroll
        for (int ks = 0; ks < 8; ++ks) {
            int kb = ks * 8;
            uint32_t a[2][4], b[4][2];
#pragma unroll
            for (int mt = 0; mt < 2; ++mt) {
                int r0 = wm + mt * 16 + gp;
                a[mt][0] = As[r0 * TLD + kb + tq];
                a[mt][1] = As[(r0 + 8) * TLD + kb + tq];
                a[mt][2] = As[r0 * TLD + kb + tq + 4];
                a[mt][3] = As[(r0 + 8) * TLD + kb + tq + 4];
            }
#pragma unroll
            for (int nt = 0; nt < 4; ++nt) {
                int c0 = wn + nt * 8 + gp;
                b[nt][0] = Bs[c0 * TLD + kb + tq];
                b[nt][1] = Bs[c0 * TLD + kb + tq + 4];
            }
#pragma unroll
            for (int mt = 0; mt < 2; ++mt)
#pragma unroll
                for (int nt = 0; nt < 4; ++nt) MMA_TF32(acc[mt][nt], a[mt], b[nt]);
        }
    }

#pragma unroll
    for (int mt = 0; mt < 2; ++mt)
#pragma unroll
        for (int nt = 0; nt < 4; ++nt) {
            int row = m0 + wm + mt * 16 + gp;
            int col = wn + nt * 8 + tq * 2;
            float b0 = bias[col], b1 = bias[col + 1];
            *(float2*)(Z + row * LAT + col) =
                make_float2(acc[mt][nt][0] + b0, acc[mt][nt][1] + b1);
            *(float2*)(Z + (row + 8) * LAT + col) =
                make_float2(acc[mt][nt][2] + b0, acc[mt][nt][3] + b1);
        }
}

// ============================================================
// fused pool + z_graph + decoded graph rows (batch sorted -> binary search)
// ============================================================
__global__ void k_poolfused(const float* __restrict__ Z, const int* __restrict__ batch,
                            float* __restrict__ z_graph,
                            const float* __restrict__ dec_w, const float* __restrict__ dec_b) {
    __shared__ float red[4][LAT];
    __shared__ float zg[LAT];
    int g = blockIdx.x;
    int tid = threadIdx.x;
    int k = tid & 63, sub = tid >> 6;

    int lo = 0, hi = N_NODES;
    while (lo < hi) { int mid = (lo + hi) >> 1; if (batch[mid] < g) lo = mid + 1; else hi = mid; }
    int start = lo;
    hi = N_NODES;
    while (lo < hi) { int mid = (lo + hi) >> 1; if (batch[mid] < g + 1) lo = mid + 1; else hi = mid; }
    int end = lo;

    float acc = 0.0f;
    for (int n = start + sub; n < end; n += 4) acc += Z[n * LAT + k];
    red[sub][k] = acc;
    __syncthreads();
    if (sub == 0) {
        float s = red[0][k] + red[1][k] + red[2][k] + red[3][k];
        float zv = s / fmaxf((float)(end - start), 1.0f);
        z_graph[g * LAT + k] = zv;
        zg[k] = zv;
    }
    __syncthreads();
    if (tid < IN_CH) {
        float s = dec_b[tid];
#pragma unroll
        for (int kk = 0; kk < LAT; kk++) s = fmaf(zg[kk], dec_w[tid * LAT + kk], s);
        g_xg[g * IN_CH + tid] = s;
    }
}

__global__ void k_xhat(const int* __restrict__ batch, float* __restrict__ x_hat) {
    int idx = blockIdx.x * blockDim.x + threadIdx.x;  // < N_NODES*32
    int node = idx >> 5;
    int g = batch[node];
    ((float4*)x_hat)[idx] = ((const float4*)g_xg)[g * 32 + (idx & 31)];
}

// ============================================================
// a_hat = sigmoid(Z @ Z^T): symmetric, upper-tri tiles only.
// Direct orientation: STG.64 straight from registers.
// Mirror orientation: smem transpose -> coalesced STG.128.
// ============================================================
#define AH_TLD 132        // transpose staging pitch (float)
#define AH_NTILE 128
#define AH_NBLK (AH_NTILE * (AH_NTILE + 1) / 2)   // 8256

__global__ __launch_bounds__(256, 2) void k_ahat(const float* __restrict__ Z,
                                                 float* __restrict__ out) {
    extern __shared__ uint32_t smbuf[];
    uint32_t* As = smbuf;                 // [128][TLD]
    uint32_t* Bs = smbuf + 128 * TLD;     // [128][TLD]

    // decode linear block -> (bm<=bn): L = bn*(bn+1)/2 + bm
    int L = blockIdx.x;
    int bn = (int)((sqrtf(8.0f * (float)L + 1.0f) - 1.0f) * 0.5f);
    while ((bn + 1) * (bn + 2) / 2 <= L) bn++;
    while (bn * (bn + 1) / 2 > L) bn--;
    int bm = L - bn * (bn + 1) / 2;

    int tid = threadIdx.x;
    const float4* Z4 = (const float4*)Z;

#pragma unroll
    for (int it = 0; it < 8; ++it) {
        int idx = tid + it * 256;       // 2048 float4 per tile
        int row = idx >> 4, q = idx & 15;
        float4 va = Z4[(bm * 128 + row) * 16 + q];
        As[row * TLD + q * 4 + 0] = f2tf32(va.x);
        As[row * TLD + q * 4 + 1] = f2tf32(va.y);
        As[row * TLD + q * 4 + 2] = f2tf32(va.z);
        As[row * TLD + q * 4 + 3] = f2tf32(va.w);
        float4 vb = Z4[(bn * 128 + row) * 16 + q];
        Bs[row * TLD + q * 4 + 0] = f2tf32(vb.x);
        Bs[row * TLD + q * 4 + 1] = f2tf32(vb.y);
        Bs[row * TLD + q * 4 + 2] = f2tf32(vb.z);
        Bs[row * TLD + q * 4 + 3] = f2tf32(vb.w);
    }
    __syncthreads();

    int warp = tid >> 5, lane = tid & 31;
    int wm = (warp >> 2) * 64;
    int wn = (warp & 3) * 32;
    int gp = lane >> 2, tq = lane & 3;

    float acc[4][4][4];
#pragma unroll
    for (int mt = 0; mt < 4; mt++)
#pragma unroll
        for (int nt = 0; nt < 4; nt++)
#pragma unroll
            for (int r = 0; r < 4; r++) acc[mt][nt][r] = 0.0f;

#pragma unroll
    for (int ks = 0; ks < 8; ++ks) {
        int kb = ks * 8;
        uint32_t a[4][4], b[4][2];
#pragma unroll
        for (int mt = 0; mt < 4; ++mt) {
            int r0 = wm + mt * 16 + gp;
            a[mt][0] = As[r0 * TLD + kb + tq];
            a[mt][1] = As[(r0 + 8) * TLD + kb + tq];
            a[mt][2] = As[r0 * TLD + kb + tq + 4];
            a[mt][3] = As[(r0 + 8) * TLD + kb + tq + 4];
        }
#pragma unroll
        for (int nt = 0; nt < 4; ++nt) {
            int c0 = wn + nt * 8 + gp;
            b[nt][0] = Bs[c0 * TLD + kb + tq];
            b[nt][1] = Bs[c0 * TLD + kb + tq + 4];
        }
#pragma unroll
        for (int mt = 0; mt < 4; ++mt)
#pragma unroll
            for (int nt = 0; nt < 4; ++nt) MMA_TF32(acc[mt][nt], a[mt], b[nt]);
    }

    // sigmoid in registers, direct STG.64 store of (bm,bn) tile
#pragma unroll
    for (int mt = 0; mt < 4; ++mt)
#pragma unroll
        for (int nt = 0; nt < 4; ++nt) {
#pragma unroll
            for (int r = 0; r < 4; ++r) acc[mt][nt][r] = fsig(acc[mt][nt][r]);
            int row = bm * 128 + wm + mt * 16 + gp;
            int col = bn * 128 + wn + nt * 8 + tq * 2;
            *(float2*)(out + (size_t)row * N_NODES + col) =
                make_float2(acc[mt][nt][0], acc[mt][nt][1]);
            *(float2*)(out + (size_t)(row + 8) * N_NODES + col) =
                make_float2(acc[mt][nt][2], acc[mt][nt][3]);
        }

    // mirror tile: transpose through smem (reuse As/Bs), coalesced STG.128
    if (bm != bn) {
        __syncthreads();
        float* S = (float*)smbuf;         // [128][AH_TLD], 67584 B
#pragma unroll
        for (int mt = 0; mt < 4; ++mt)
#pragma unroll
            for (int nt = 0; nt < 4; ++nt) {
                int rl = wm + mt * 16 + gp;
                int cl = wn + nt * 8 + tq * 2;
                S[cl * AH_TLD + rl]           = acc[mt][nt][0];
                S[(cl + 1) * AH_TLD + rl]     = acc[mt][nt][1];
                S[cl * AH_TLD + rl + 8]       = acc[mt][nt][2];
                S[(cl + 1) * AH_TLD + rl + 8] = acc[mt][nt][3];
            }
        __syncthreads();
#pragma unroll
        for (int it = 0; it < 16; ++it) {
            int idx = tid + it * 256;     // 4096 float4
            int rt = idx >> 5, q = idx & 31;
            float4 w = *(const float4*)(S + rt * AH_TLD + q * 4);
            *(float4*)(out + (size_t)(bn * 128 + rt) * N_NODES + bm * 128 + q * 4) = w;
        }
    }
}

// ============================================================
// launch
// ============================================================
extern "C" void kernel_launch(void* const* d_in, const int* in_sizes, int n_in,
                              void* d_out, int out_size) {
    const float* x     = (const float*)d_in[0];
    const int*   ei    = (const int*)d_in[1];    // int32
    const int*   batch = (const int*)d_in[2];    // int32, sorted
    const float* gcn_w = (const float*)d_in[3];
    const float* gcn_b = (const float*)d_in[4];
    const float* lin_w = (const float*)d_in[5];
    const float* lin_b = (const float*)d_in[6];
    const float* dec_w = (const float*)d_in[7];
    const float* dec_b = (const float*)d_in[8];

    float* out     = (float*)d_out;
    float* z_node  = out;
    float* z_graph = out + 1048576;
    float* x_hat   = out + 1049600;
    float* a_hat   = out + 3146752;

    const int SMEM_2T = 2 * 128 * TLD * 4;             // 69632 B (ahat, gemm1)
    const int SMEM_G2 = (128 + 64) * TLD * 4;          // 52224 B (gemm2)
    cudaFuncSetAttribute(k_ahat,  cudaFuncAttributeMaxDynamicSharedMemorySize, SMEM_2T);
    cudaFuncSetAttribute(k_gemm1, cudaFuncAttributeMaxDynamicSharedMemorySize, SMEM_2T);
    cudaFuncSetAttribute(k_gemm2, cudaFuncAttributeMaxDynamicSharedMemorySize, SMEM_G2);

    k_init<<<64, 256>>>();
    k_degree<<<1024, 256>>>(ei);
    k_scale<<<2048, 256>>>((const float4*)x);
    k_scatter<<<32768, 256>>>(ei);
    k_gemm1<<<dim3(2, 128), 256, SMEM_2T>>>(gcn_w, gcn_b);
    k_gemm2<<<128, 256, SMEM_G2>>>(lin_w, lin_b, z_node);
    k_poolfused<<<N_GRAPHS, 256>>>(z_node, batch, z_graph, dec_w, dec_b);
    k_xhat<<<2048, 256>>>(batch, x_hat);
    k_ahat<<<AH_NBLK, 256, SMEM_2T>>>(z_node, a_hat);
}

// round 8
// speedup vs baseline: 3.0398x; 1.1280x over previous
#include <cuda_runtime.h>
#include <cstdint>
#include <cmath>

#define N_NODES 16384
#define N_EDGES 262144
#define N_GRAPHS 16
#define IN_CH 128
#define HID_CH 256
#define LAT 64

// ---- output layout (tuple flattened, all fp32) ----
// z_node  [16384,64]   @ 0
// z_graph [16,64]      @ 1048576
// x_hat   [16384,128]  @ 1049600
// a_hat   [16384,16384]@ 3146752

// ---- device scratch ----
__device__ float g_dinv[N_NODES];                        // degree, then rsqrt(degree)
__device__ __align__(16) float g_agg[N_NODES * IN_CH];   // sum incoming + self
__device__ __align__(16) float g_h  [N_NODES * HID_CH];  // relu hidden
__device__ __align__(16) float g_xg [N_GRAPHS * IN_CH];  // decoded per-graph row

__device__ __forceinline__ uint32_t f2tf32(float f) {
    uint32_t u;
    asm("cvt.rna.tf32.f32 %0, %1;" : "=r"(u) : "f"(f));
    return u;
}
__device__ __forceinline__ float fsig(float x) {
    float t;
    asm("tanh.approx.f32 %0, %1;" : "=f"(t) : "f"(x * 0.5f));
    return fmaf(t, 0.5f, 0.5f);
}
#define MMA_TF32(acc, a, b)                                                    \
    asm volatile(                                                              \
        "mma.sync.aligned.m16n8k8.row.col.f32.tf32.tf32.f32 "                  \
        "{%0,%1,%2,%3}, {%4,%5,%6,%7}, {%8,%9}, {%0,%1,%2,%3};"                \
        : "+f"(acc[0]), "+f"(acc[1]), "+f"(acc[2]), "+f"(acc[3])               \
        : "r"(a[0]), "r"(a[1]), "r"(a[2]), "r"(a[3]), "r"(b[0]), "r"(b[1]))

#define TLD 68   // tf32 smem pitch (uint32)

// ============================================================
__global__ void k_init() {
    int i = blockIdx.x * blockDim.x + threadIdx.x;
    if (i < N_NODES) g_dinv[i] = 1.0f;               // self-loop degree
}

__global__ void k_degree(const int* __restrict__ ei) {
    int e = blockIdx.x * blockDim.x + threadIdx.x;
    if (e < N_EDGES) atomicAdd(&g_dinv[ei[N_EDGES + e]], 1.0f);
}

// d = rsqrt(deg); agg init = d*x (self-loop term); store d back
__global__ void k_scale(const float4* __restrict__ x4) {
    int idx = blockIdx.x * blockDim.x + threadIdx.x; // < N_NODES*32
    int node = idx >> 5;
    int lane = idx & 31;
    float d = rsqrtf(g_dinv[node]);
    float4 v = x4[idx];
    v.x *= d; v.y *= d; v.z *= d; v.w *= d;
    ((float4*)g_agg)[idx] = v;
    if (lane == 0) g_dinv[node] = d;
}

// one warp per edge: 32 lanes x float4 = 128 ch; dinv applied on the fly
__global__ void k_scatter(const int* __restrict__ ei, const float4* __restrict__ x4) {
    int gid = blockIdx.x * blockDim.x + threadIdx.x;
    int e = gid >> 5;
    int lane = gid & 31;
    if (e >= N_EDGES) return;
    int r = ei[e];
    int c = ei[N_EDGES + e];
    float d = g_dinv[r];
    float4 v = x4[r * 32 + lane];
    v.x *= d; v.y *= d; v.z *= d; v.w *= d;
    atomicAdd((float4*)(g_agg + c * IN_CH + lane * 4), v);
}

// ============================================================
// GEMM1 (tf32 MMA): h = relu( (dinv.*agg)[16384,128] @ gcn_w[256,128]^T + b )
// block 128x128, 8 warps (2x4), warp 64x32, K chunked 64 (2 chunks)
// ============================================================
__global__ __launch_bounds__(256, 2) void k_gemm1(const float* __restrict__ W,
                                                  const float* __restrict__ bias) {
    extern __shared__ uint32_t smbuf[];
    uint32_t* As = smbuf;               // [128][TLD]
    uint32_t* Bs = smbuf + 128 * TLD;   // [128][TLD]
    int m0 = blockIdx.y * 128, n0 = blockIdx.x * 128;
    int tid = threadIdx.x;
    int warp = tid >> 5, lane = tid & 31;
    int wm = (warp >> 2) * 64, wn = (warp & 3) * 32;
    int gp = lane >> 2, tq = lane & 3;

    float acc[4][4][4];
#pragma unroll
    for (int mt = 0; mt < 4; mt++)
#pragma unroll
        for (int nt = 0; nt < 4; nt++)
#pragma unroll
            for (int r = 0; r < 4; r++) acc[mt][nt][r] = 0.0f;

#pragma unroll
    for (int kc = 0; kc < IN_CH; kc += 64) {
        if (kc) __syncthreads();
#pragma unroll
        for (int it = 0; it < 8; ++it) {
            int idx = tid + it * 256;       // 2048 float4 per 128x64 tile
            int row = idx >> 4, q = idx & 15;
            float4 va = ((const float4*)g_agg)[(m0 + row) * (IN_CH / 4) + (kc >> 2) + q];
            float d = g_dinv[m0 + row];
            As[row * TLD + q * 4 + 0] = f2tf32(va.x * d);
            As[row * TLD + q * 4 + 1] = f2tf32(va.y * d);
            As[row * TLD + q * 4 + 2] = f2tf32(va.z * d);
            As[row * TLD + q * 4 + 3] = f2tf32(va.w * d);
            float4 vb = ((const float4*)W)[(n0 + row) * (IN_CH / 4) + (kc >> 2) + q];
            Bs[row * TLD + q * 4 + 0] = f2tf32(vb.x);
            Bs[row * TLD + q * 4 + 1] = f2tf32(vb.y);
            Bs[row * TLD + q * 4 + 2] = f2tf32(vb.z);
            Bs[row * TLD + q * 4 + 3] = f2tf32(vb.w);
        }
        __syncthreads();
#pragma unroll
        for (int ks = 0; ks < 8; ++ks) {
            int kb = ks * 8;
            uint32_t a[4][4], b[4][2];
#pragma unroll
            for (int mt = 0; mt < 4; ++mt) {
                int r0 = wm + mt * 16 + gp;
                a[mt][0] = As[r0 * TLD + kb + tq];
                a[mt][1] = As[(r0 + 8) * TLD + kb + tq];
                a[mt][2] = As[r0 * TLD + kb + tq + 4];
                a[mt][3] = As[(r0 + 8) * TLD + kb + tq + 4];
            }
#pragma unroll
            for (int nt = 0; nt < 4; ++nt) {
                int c0 = wn + nt * 8 + gp;
                b[nt][0] = Bs[c0 * TLD + kb + tq];
                b[nt][1] = Bs[c0 * TLD + kb + tq + 4];
            }
#pragma unroll
            for (int mt = 0; mt < 4; ++mt)
#pragma unroll
                for (int nt = 0; nt < 4; ++nt) MMA_TF32(acc[mt][nt], a[mt], b[nt]);
        }
    }

#pragma unroll
    for (int mt = 0; mt < 4; ++mt)
#pragma unroll
        for (int nt = 0; nt < 4; ++nt) {
            int row = m0 + wm + mt * 16 + gp;
            int col = n0 + wn + nt * 8 + tq * 2;
            float b0 = bias[col], b1 = bias[col + 1];
            *(float2*)(g_h + row * HID_CH + col) =
                make_float2(fmaxf(acc[mt][nt][0] + b0, 0.0f), fmaxf(acc[mt][nt][1] + b1, 0.0f));
            *(float2*)(g_h + (row + 8) * HID_CH + col) =
                make_float2(fmaxf(acc[mt][nt][2] + b0, 0.0f), fmaxf(acc[mt][nt][3] + b1, 0.0f));
        }
}

// ============================================================
// GEMM2 (tf32 MMA): z_node = h[16384,256] @ lin_w[64,256]^T + lin_b
// block 128x64, 8 warps (4x2), warp 32x32, K chunked 64 (4 chunks)
// ============================================================
__global__ __launch_bounds__(256) void k_gemm2(const float* __restrict__ W,
                                               const float* __restrict__ bias,
                                               float* __restrict__ Z) {
    extern __shared__ uint32_t smbuf[];
    uint32_t* As = smbuf;               // [128][TLD]
    uint32_t* Bs = smbuf + 128 * TLD;   // [64][TLD]
    int m0 = blockIdx.x * 128;
    int tid = threadIdx.x;
    int warp = tid >> 5, lane = tid & 31;
    int wm = (warp >> 1) * 32, wn = (warp & 1) * 32;
    int gp = lane >> 2, tq = lane & 3;

    float acc[2][4][4];
#pragma unroll
    for (int mt = 0; mt < 2; mt++)
#pragma unroll
        for (int nt = 0; nt < 4; nt++)
#pragma unroll
            for (int r = 0; r < 4; r++) acc[mt][nt][r] = 0.0f;

#pragma unroll
    for (int kc = 0; kc < HID_CH; kc += 64) {
        if (kc) __syncthreads();
#pragma unroll
        for (int it = 0; it < 8; ++it) {
            int idx = tid + it * 256;       // A: 2048 float4
            int row = idx >> 4, q = idx & 15;
            float4 va = ((const float4*)g_h)[(m0 + row) * (HID_CH / 4) + (kc >> 2) + q];
            As[row * TLD + q * 4 + 0] = f2tf32(va.x);
            As[row * TLD + q * 4 + 1] = f2tf32(va.y);
            As[row * TLD + q * 4 + 2] = f2tf32(va.z);
            As[row * TLD + q * 4 + 3] = f2tf32(va.w);
        }
#pragma unroll
        for (int it = 0; it < 4; ++it) {
            int idx = tid + it * 256;       // B: 1024 float4
            int row = idx >> 4, q = idx & 15;
            float4 vb = ((const float4*)W)[row * (HID_CH / 4) + (kc >> 2) + q];
            Bs[row * TLD + q * 4 + 0] = f2tf32(vb.x);
            Bs[row * TLD + q * 4 + 1] = f2tf32(vb.y);
            Bs[row * TLD + q * 4 + 2] = f2tf32(vb.z);
            Bs[row * TLD + q * 4 + 3] = f2tf32(vb.w);
        }
        __syncthreads();
#pragma unroll
        for (int ks = 0; ks < 8; ++ks) {
            int kb = ks * 8;
            uint32_t a[2][4], b[4][2];
#pragma unroll
            for (int mt = 0; mt < 2; ++mt) {
                int r0 = wm + mt * 16 + gp;
                a[mt][0] = As[r0 * TLD + kb + tq];
                a[mt][1] = As[(r0 + 8) * TLD + kb + tq];
                a[mt][2] = As[r0 * TLD + kb + tq + 4];
                a[mt][3] = As[(r0 + 8) * TLD + kb + tq + 4];
            }
#pragma unroll
            for (int nt = 0; nt < 4; ++nt) {
                int c0 = wn + nt * 8 + gp;
                b[nt][0] = Bs[c0 * TLD + kb + tq];
                b[nt][1] = Bs[c0 * TLD + kb + tq + 4];
            }
#pragma unroll
            for (int mt = 0; mt < 2; ++mt)
#pragma unroll
                for (int nt = 0; nt < 4; ++nt) MMA_TF32(acc[mt][nt], a[mt], b[nt]);
        }
    }

#pragma unroll
    for (int mt = 0; mt < 2; ++mt)
#pragma unroll
        for (int nt = 0; nt < 4; ++nt) {
            int row = m0 + wm + mt * 16 + gp;
            int col = wn + nt * 8 + tq * 2;
            float b0 = bias[col], b1 = bias[col + 1];
            *(float2*)(Z + row * LAT + col) =
                make_float2(acc[mt][nt][0] + b0, acc[mt][nt][1] + b1);
            *(float2*)(Z + (row + 8) * LAT + col) =
                make_float2(acc[mt][nt][2] + b0, acc[mt][nt][3] + b1);
        }
}

// ============================================================
// fused pool + z_graph + decoded graph rows (batch sorted -> binary search)
// ============================================================
__global__ void k_poolfused(const float* __restrict__ Z, const int* __restrict__ batch,
                            float* __restrict__ z_graph,
                            const float* __restrict__ dec_w, const float* __restrict__ dec_b) {
    __shared__ float red[4][LAT];
    __shared__ float zg[LAT];
    int g = blockIdx.x;
    int tid = threadIdx.x;
    int k = tid & 63, sub = tid >> 6;

    int lo = 0, hi = N_NODES;
    while (lo < hi) { int mid = (lo + hi) >> 1; if (batch[mid] < g) lo = mid + 1; else hi = mid; }
    int start = lo;
    hi = N_NODES;
    while (lo < hi) { int mid = (lo + hi) >> 1; if (batch[mid] < g + 1) lo = mid + 1; else hi = mid; }
    int end = lo;

    float acc = 0.0f;
    for (int n = start + sub; n < end; n += 4) acc += Z[n * LAT + k];
    red[sub][k] = acc;
    __syncthreads();
    if (sub == 0) {
        float s = red[0][k] + red[1][k] + red[2][k] + red[3][k];
        float zv = s / fmaxf((float)(end - start), 1.0f);
        z_graph[g * LAT + k] = zv;
        zg[k] = zv;
    }
    __syncthreads();
    if (tid < IN_CH) {
        float s = dec_b[tid];
#pragma unroll
        for (int kk = 0; kk < LAT; kk++) s = fmaf(zg[kk], dec_w[tid * LAT + kk], s);
        g_xg[g * IN_CH + tid] = s;
    }
}

__global__ void k_xhat(const int* __restrict__ batch, float* __restrict__ x_hat) {
    int idx = blockIdx.x * blockDim.x + threadIdx.x;  // < N_NODES*32
    int node = idx >> 5;
    int g = batch[node];
    ((float4*)x_hat)[idx] = ((const float4*)g_xg)[g * 32 + (idx & 31)];
}

// ============================================================
// a_hat = sigmoid(Z @ Z^T): symmetric, upper-tri tiles only.
// Direct orientation: streaming STG.64 from registers.
// Mirror orientation: smem transpose -> streaming STG.128.
// ============================================================
#define AH_TLD 132        // transpose staging pitch (float)
#define AH_NTILE 128
#define AH_NBLK (AH_NTILE * (AH_NTILE + 1) / 2)   // 8256

__global__ __launch_bounds__(256, 2) void k_ahat(const float* __restrict__ Z,
                                                 float* __restrict__ out) {
    extern __shared__ uint32_t smbuf[];
    uint32_t* As = smbuf;                 // [128][TLD]
    uint32_t* Bs = smbuf + 128 * TLD;     // [128][TLD]

    // decode linear block -> (bm<=bn): L = bn*(bn+1)/2 + bm
    int L = blockIdx.x;
    int bn = (int)((sqrtf(8.0f * (float)L + 1.0f) - 1.0f) * 0.5f);
    while ((bn + 1) * (bn + 2) / 2 <= L) bn++;
    while (bn * (bn + 1) / 2 > L) bn--;
    int bm = L - bn * (bn + 1) / 2;

    int tid = threadIdx.x;
    const float4* Z4 = (const float4*)Z;

#pragma unroll
    for (int it = 0; it < 8; ++it) {
        int idx = tid + it * 256;       // 2048 float4 per tile
        int row = idx >> 4, q = idx & 15;
        float4 va = Z4[(bm * 128 + row) * 16 + q];
        As[row * TLD + q * 4 + 0] = f2tf32(va.x);
        As[row * TLD + q * 4 + 1] = f2tf32(va.y);
        As[row * TLD + q * 4 + 2] = f2tf32(va.z);
        As[row * TLD + q * 4 + 3] = f2tf32(va.w);
        float4 vb = Z4[(bn * 128 + row) * 16 + q];
        Bs[row * TLD + q * 4 + 0] = f2tf32(vb.x);
        Bs[row * TLD + q * 4 + 1] = f2tf32(vb.y);
        Bs[row * TLD + q * 4 + 2] = f2tf32(vb.z);
        Bs[row * TLD + q * 4 + 3] = f2tf32(vb.w);
    }
    __syncthreads();

    int warp = tid >> 5, lane = tid & 31;
    int wm = (warp >> 2) * 64;
    int wn = (warp & 3) * 32;
    int gp = lane >> 2, tq = lane & 3;

    float acc[4][4][4];
#pragma unroll
    for (int mt = 0; mt < 4; mt++)
#pragma unroll
        for (int nt = 0; nt < 4; nt++)
#pragma unroll
            for (int r = 0; r < 4; r++) acc[mt][nt][r] = 0.0f;

#pragma unroll
    for (int ks = 0; ks < 8; ++ks) {
        int kb = ks * 8;
        uint32_t a[4][4], b[4][2];
#pragma unroll
        for (int mt = 0; mt < 4; ++mt) {
            int r0 = wm + mt * 16 + gp;
            a[mt][0] = As[r0 * TLD + kb + tq];
            a[mt][1] = As[(r0 + 8) * TLD + kb + tq];
            a[mt][2] = As[r0 * TLD + kb + tq + 4];
            a[mt][3] = As[(r0 + 8) * TLD + kb + tq + 4];
        }
#pragma unroll
        for (int nt = 0; nt < 4; ++nt) {
            int c0 = wn + nt * 8 + gp;
            b[nt][0] = Bs[c0 * TLD + kb + tq];
            b[nt][1] = Bs[c0 * TLD + kb + tq + 4];
        }
#pragma unroll
        for (int mt = 0; mt < 4; ++mt)
#pragma unroll
            for (int nt = 0; nt < 4; ++nt) MMA_TF32(acc[mt][nt], a[mt], b[nt]);
    }

    // sigmoid in registers, streaming STG.64 store of (bm,bn) tile
#pragma unroll
    for (int mt = 0; mt < 4; ++mt)
#pragma unroll
        for (int nt = 0; nt < 4; ++nt) {
#pragma unroll
            for (int r = 0; r < 4; ++r) acc[mt][nt][r] = fsig(acc[mt][nt][r]);
            int row = bm * 128 + wm + mt * 16 + gp;
            int col = bn * 128 + wn + nt * 8 + tq * 2;
            __stcs((float2*)(out + (size_t)row * N_NODES + col),
                   make_float2(acc[mt][nt][0], acc[mt][nt][1]));
            __stcs((float2*)(out + (size_t)(row + 8) * N_NODES + col),
                   make_float2(acc[mt][nt][2], acc[mt][nt][3]));
        }

    // mirror tile: transpose through smem (reuse As/Bs), streaming STG.128
    if (bm != bn) {
        __syncthreads();
        float* S = (float*)smbuf;         // [128][AH_TLD], 67584 B
#pragma unroll
        for (int mt = 0; mt < 4; ++mt)
#pragma unroll
            for (int nt = 0; nt < 4; ++nt) {
                int rl = wm + mt * 16 + gp;
                int cl = wn + nt * 8 + tq * 2;
                S[cl * AH_TLD + rl]           = acc[mt][nt][0];
                S[(cl + 1) * AH_TLD + rl]     = acc[mt][nt][1];
                S[cl * AH_TLD + rl + 8]       = acc[mt][nt][2];
                S[(cl + 1) * AH_TLD + rl + 8] = acc[mt][nt][3];
            }
        __syncthreads();
#pragma unroll
        for (int it = 0; it < 16; ++it) {
            int idx = tid + it * 256;     // 4096 float4
            int rt = idx >> 5, q = idx & 31;
            float4 w = *(const float4*)(S + rt * AH_TLD + q * 4);
            __stcs((float4*)(out + (size_t)(bn * 128 + rt) * N_NODES + bm * 128 + q * 4), w);
        }
    }
}

// ============================================================
// launch: pool+xhat forked to a side stream, overlapped with k_ahat
// ============================================================
extern "C" void kernel_launch(void* const* d_in, const int* in_sizes, int n_in,
                              void* d_out, int out_size) {
    const float* x     = (const float*)d_in[0];
    const int*   ei    = (const int*)d_in[1];    // int32
    const int*   batch = (const int*)d_in[2];    // int32, sorted
    const float* gcn_w = (const float*)d_in[3];
    const float* gcn_b = (const float*)d_in[4];
    const float* lin_w = (const float*)d_in[5];
    const float* lin_b = (const float*)d_in[6];
    const float* dec_w = (const float*)d_in[7];
    const float* dec_b = (const float*)d_in[8];

    float* out     = (float*)d_out;
    float* z_node  = out;
    float* z_graph = out + 1048576;
    float* x_hat   = out + 1049600;
    float* a_hat   = out + 3146752;

    static cudaStream_t s2 = nullptr;
    static cudaEvent_t eFork = nullptr, eJoin = nullptr;
    if (!s2) {
        cudaStreamCreateWithFlags(&s2, cudaStreamNonBlocking);
        cudaEventCreateWithFlags(&eFork, cudaEventDisableTiming);
        cudaEventCreateWithFlags(&eJoin, cudaEventDisableTiming);
        const int SMEM_2T = 2 * 128 * TLD * 4;       // 69632 B
        const int SMEM_G2 = (128 + 64) * TLD * 4;    // 52224 B
        cudaFuncSetAttribute(k_ahat,  cudaFuncAttributeMaxDynamicSharedMemorySize, SMEM_2T);
        cudaFuncSetAttribute(k_gemm1, cudaFuncAttributeMaxDynamicSharedMemorySize, SMEM_2T);
        cudaFuncSetAttribute(k_gemm2, cudaFuncAttributeMaxDynamicSharedMemorySize, SMEM_G2);
    }
    const int SMEM_2T = 2 * 128 * TLD * 4;
    const int SMEM_G2 = (128 + 64) * TLD * 4;

    k_init<<<64, 256>>>();
    k_degree<<<1024, 256>>>(ei);
    k_scale<<<2048, 256>>>((const float4*)x);
    k_scatter<<<32768, 256>>>(ei, (const float4*)x);
    k_gemm1<<<dim3(2, 128), 256, SMEM_2T>>>(gcn_w, gcn_b);
    k_gemm2<<<128, 256, SMEM_G2>>>(lin_w, lin_b, z_node);

    // fork: pool + xhat run on s2 concurrently with k_ahat on the main stream
    cudaEventRecord(eFork, 0);
    cudaStreamWaitEvent(s2, eFork, 0);
    k_poolfused<<<N_GRAPHS, 256, 0, s2>>>(z_node, batch, z_graph, dec_w, dec_b);
    k_xhat<<<2048, 256, 0, s2>>>(batch, x_hat);
    cudaEventRecord(eJoin, s2);

    k_ahat<<<AH_NBLK, 256, SMEM_2T>>>(z_node, a_hat);

    // join
    cudaStreamWaitEvent(0, eJoin, 0);
}